// round 7
// baseline (speedup 1.0000x reference)
#include <cuda_runtime.h>
#include <math.h>
#include <stdint.h>

#define Bsz 2
#define Tt  2048
#define Cc  1024
#define Hh  16
#define KVh 4
#define HDim 64
#define QKVN 1536   // 1024 Q + 256 K + 256 V

// -------- scratch (static device globals; no allocation) --------
__device__ float g_Xtf[Bsz * Tt * Cc];         // x pre-converted to tf32 bits
__device__ float g_QKV[Bsz * Tt * QKVN];       // fused Q|K|V rows (fp32)
__device__ float g_Y[Bsz * Tt * Hh * HDim];    // attention out (tf32 bits)
__device__ float g_WqkvT[QKVN * Cc];           // transposed + tf32 bits
__device__ float g_WoT[Cc * Cc];               // transposed + tf32 bits

__device__ __forceinline__ uint32_t f2tf32(float f) {
    uint32_t r;
    asm("cvt.rna.tf32.f32 %0, %1;" : "=r"(r) : "f"(f));
    return r;
}
__device__ __forceinline__ float tf(float f) { return __uint_as_float(f2tf32(f)); }

__device__ __forceinline__ void mma4(float* c,
    uint32_t a0, uint32_t a1, uint32_t a2, uint32_t a3,
    uint32_t b0, uint32_t b1) {
    asm volatile(
        "mma.sync.aligned.m16n8k8.row.col.f32.tf32.tf32.f32 "
        "{%0,%1,%2,%3}, {%4,%5,%6,%7}, {%8,%9}, {%0,%1,%2,%3};"
        : "+f"(c[0]), "+f"(c[1]), "+f"(c[2]), "+f"(c[3])
        : "r"(a0), "r"(a1), "r"(a2), "r"(a3), "r"(b0), "r"(b1));
}

// ldmatrix x4 on tf32 data: one call = one A-fragment (16x8) or two
// B-fragments (2 x 8x8). Result regs: r0=[r, c] r1=[r, c+4] r2=[r+8, c]
// r3=[r+8, c+4] in the m8n8 b16 double-tile view.
__device__ __forceinline__ void ldmx4(uint32_t* r, uint32_t saddr) {
    asm volatile("ldmatrix.sync.aligned.m8n8.x4.shared.b16 {%0,%1,%2,%3}, [%4];"
        : "=r"(r[0]), "=r"(r[1]), "=r"(r[2]), "=r"(r[3]) : "r"(saddr));
}

__device__ __forceinline__ void cpa16(float* s, const float* g) {
    uint32_t sa = (uint32_t)__cvta_generic_to_shared(s);
    asm volatile("cp.async.ca.shared.global [%0], [%1], 16;" :: "r"(sa), "l"(g));
}
#define CP_COMMIT() asm volatile("cp.async.commit_group;" ::: "memory")
#define CP_WAIT(n)  asm volatile("cp.async.wait_group %0;" :: "n"(n) : "memory")

// ============================================================
// x -> tf32 bits (vectorized)
// ============================================================
__global__ __launch_bounds__(256) void cvt_x(
    const float* __restrict__ in, float* __restrict__ out)
{
    int i = blockIdx.x * blockDim.x + threadIdx.x;
    float4 v = *(const float4*)(in + (size_t)i * 4);
    float4 o = { tf(v.x), tf(v.y), tf(v.z), tf(v.w) };
    *(float4*)(out + (size_t)i * 4) = o;
}

// ============================================================
// Fused QKV weight transpose + tf32 cvt
// ============================================================
__global__ __launch_bounds__(256) void transpose_qkv(
    const float* __restrict__ Wq, const float* __restrict__ Wk,
    const float* __restrict__ Wv, float* __restrict__ out)
{
    __shared__ float tile[32][33];
    int nblk = blockIdx.x;
    int k0 = blockIdx.y * 32;
    int tx = threadIdx.x, ty = threadIdx.y;

    const float* src;
    int N, nloc;
    if (nblk < 32)      { src = Wq; N = 1024; nloc = nblk * 32; }
    else if (nblk < 40) { src = Wk; N = 256;  nloc = (nblk - 32) * 32; }
    else                { src = Wv; N = 256;  nloc = (nblk - 40) * 32; }

#pragma unroll
    for (int i = 0; i < 32; i += 8)
        tile[ty + i][tx] = src[(size_t)(k0 + ty + i) * N + nloc + tx];
    __syncthreads();
#pragma unroll
    for (int i = 0; i < 32; i += 8)
        out[(size_t)(nblk * 32 + ty + i) * Cc + k0 + tx] = tf(tile[tx][ty + i]);
}

__global__ __launch_bounds__(256) void transpose_k(
    const float* __restrict__ in, float* __restrict__ out, int K, int N)
{
    __shared__ float tile[32][33];
    int k0 = blockIdx.y * 32, n0 = blockIdx.x * 32;
    int tx = threadIdx.x, ty = threadIdx.y;
#pragma unroll
    for (int i = 0; i < 32; i += 8)
        tile[ty + i][tx] = in[(size_t)(k0 + ty + i) * N + n0 + tx];
    __syncthreads();
#pragma unroll
    for (int i = 0; i < 32; i += 8)
        out[(size_t)(n0 + ty + i) * K + k0 + tx] = tf(tile[tx][ty + i]);
}

// ============================================================
// Pipelined tf32 mma.sync GEMM, ldmatrix fragment loads.
// ============================================================
#define SMS 36
#define STAGE_F (2 * 128 * SMS)
#define GEMM_SMEM (3 * STAGE_F * 4)

__global__ __launch_bounds__(256, 2) void gemm_mma(
    const float* __restrict__ A, const float* __restrict__ BT,
    float* __restrict__ C, int M, int N, int K)
{
    extern __shared__ float sh[];

    int tid = threadIdx.x;
    int wid = tid >> 5;
    int lane = tid & 31;
    int gr = lane >> 2;
    int gc = lane & 3;
    int bm = blockIdx.y * 128, bn = blockIdx.x * 128;
    int m0 = (wid & 1) * 64;
    int n0 = (wid >> 1) * 32;

    // ldmatrix per-lane address offsets
    const int aro = ((lane & 16) ? 8 : 0) + (lane & 7);   // row offset
    const int aco = (lane & 8) ? 4 : 0;                   // col offset

    const int crow = tid >> 3;
    const int ccol = (tid & 7) * 4;

    const uint32_t sh_u32 = (uint32_t)__cvta_generic_to_shared(sh);

    float acc[4][4][4];
#pragma unroll
    for (int mt = 0; mt < 4; mt++)
#pragma unroll
        for (int nt = 0; nt < 4; nt++)
#pragma unroll
            for (int i = 0; i < 4; i++) acc[mt][nt][i] = 0.f;

    auto issue = [&](int s, int kc) {
        float* As = sh + s * STAGE_F;
        float* Bs = As + 128 * SMS;
#pragma unroll
        for (int i = 0; i < 4; i++) {
            int row = i * 32 + crow;
            cpa16(&As[row * SMS + ccol], A  + (size_t)(bm + row) * K + kc + ccol);
            cpa16(&Bs[row * SMS + ccol], BT + (size_t)(bn + row) * K + kc + ccol);
        }
        CP_COMMIT();
    };

    const int NCH = K / 32;
    issue(0, 0);
    issue(1, 32);

    int s = 0;
    for (int c = 0; c < NCH; c++) {
        if (c == NCH - 1) { CP_WAIT(0); } else { CP_WAIT(1); }
        __syncthreads();
        if (c + 2 < NCH) {
            int s2 = s + 2; if (s2 >= 3) s2 -= 3;
            issue(s2, (c + 2) * 32);
        }

        uint32_t As_u = sh_u32 + s * STAGE_F * 4;
        uint32_t Bs_u = As_u + 128 * SMS * 4;
#pragma unroll
        for (int ks = 0; ks < 4; ks++) {
            int k0 = ks * 8;
            uint32_t am[4][4], bmx[2][4];
#pragma unroll
            for (int mt = 0; mt < 4; mt++)
                ldmx4(am[mt], As_u + 4 * ((m0 + mt * 16 + aro) * SMS + k0 + aco));
#pragma unroll
            for (int p = 0; p < 2; p++)
                ldmx4(bmx[p], Bs_u + 4 * ((n0 + p * 16 + aro) * SMS + k0 + aco));
#pragma unroll
            for (int mt = 0; mt < 4; mt++)
#pragma unroll
                for (int nt = 0; nt < 4; nt++) {
                    int p = nt >> 1, h = nt & 1;
                    mma4(acc[mt][nt],
                         am[mt][0], am[mt][2], am[mt][1], am[mt][3],
                         bmx[p][2 * h], bmx[p][2 * h + 1]);
                }
        }
        if (++s >= 3) s -= 3;
    }

#pragma unroll
    for (int mt = 0; mt < 4; mt++) {
#pragma unroll
        for (int nt = 0; nt < 4; nt++) {
            int row = bm + m0 + mt * 16 + gr;
            int col = bn + n0 + nt * 8 + 2 * gc;
            *(float2*)&C[(size_t)row * N + col] =
                make_float2(acc[mt][nt][0], acc[mt][nt][1]);
            *(float2*)&C[(size_t)(row + 8) * N + col] =
                make_float2(acc[mt][nt][2], acc[mt][nt][3]);
        }
    }
}

// ============================================================
// RoPE + RMSNorm over fused QKV buffer (stride QKVN).
// ============================================================
__global__ __launch_bounds__(256) void rope_rms(
    float* __restrict__ QKV,
    const float* __restrict__ cosp, const float* __restrict__ sinp)
{
    int gw = (blockIdx.x * blockDim.x + threadIdx.x) >> 5;
    int lane = threadIdx.x & 31;
    const int total_q = Bsz * Tt * Hh;

    float* p;
    int t;
    if (gw < total_q) {
        int bt = gw / Hh, h = gw % Hh;
        t = bt % Tt;
        p = QKV + (size_t)bt * QKVN + h * HDim;
    } else {
        int g = gw - total_q;
        int bt = g / KVh, kv = g % KVh;
        t = bt % Tt;
        p = QKV + (size_t)bt * QKVN + 1024 + kv * HDim;
    }

    float c = cosp[t * (HDim / 2) + lane];
    float s = sinp[t * (HDim / 2) + lane];
    float x1 = p[lane];
    float x2 = p[lane + 32];
    float o1 = x1 * c + x2 * s;
    float o2 = -x1 * s + x2 * c;

    float ss = o1 * o1 + o2 * o2;
#pragma unroll
    for (int off = 16; off > 0; off >>= 1)
        ss += __shfl_xor_sync(0xffffffffu, ss, off);

    float inv = rsqrtf(ss * (1.0f / HDim) + 1e-6f);
    p[lane]      = o1 * inv;
    p[lane + 32] = o2 * inv;
}

// ============================================================
// tf32 mma.sync flash attention with ldmatrix Q/K/P frags.
// ============================================================
#define AST 68

__global__ __launch_bounds__(256) void flash_attn_mma(
    const float* __restrict__ QKV, float* __restrict__ Og)
{
    extern __shared__ float sm[];
    float* Qs = sm;
    float* Ks = sm + 128 * AST;
    float* Vs = Ks + 64 * AST;

    int qb = blockIdx.x, h = blockIdx.y, b = blockIdx.z;
    int q0 = qb * 128;
    int kvh = h >> 2;
    int tid = threadIdx.x, wid = tid >> 5, lane = tid & 31;
    int gr = lane >> 2, gc = lane & 3;
    int m0 = wid * 16;
    const int aro = ((lane & 16) ? 8 : 0) + (lane & 7);
    const int aco = (lane & 8) ? 4 : 0;

    const uint32_t Qs_u = (uint32_t)__cvta_generic_to_shared(Qs);
    const uint32_t Ks_u = (uint32_t)__cvta_generic_to_shared(Ks);

    const float* Qbase = QKV + (size_t)(b * Tt + q0) * QKVN + h * HDim;
#pragma unroll
    for (int i = 0; i < 8; i++) {
        int fi = i * 256 + tid;
        int row = fi >> 4, c4 = (fi & 15) * 4;
        float4 v = *(const float4*)(Qbase + (size_t)row * QKVN + c4);
        float* d = &Qs[row * AST + c4];
        d[0] = tf(v.x * 0.125f); d[1] = tf(v.y * 0.125f);
        d[2] = tf(v.z * 0.125f); d[3] = tf(v.w * 0.125f);
    }
    __syncthreads();

    uint32_t qf[8][4];   // {a0,a1,a2,a3} in ldmatrix order r0,r2,r1,r3 applied at use
#pragma unroll
    for (int ks = 0; ks < 8; ks++)
        ldmx4(qf[ks], Qs_u + 4 * ((m0 + aro) * AST + ks * 8 + aco));
    __syncthreads();

    float o[8][4];
#pragma unroll
    for (int nt = 0; nt < 8; nt++)
#pragma unroll
        for (int i = 0; i < 4; i++) o[nt][i] = 0.f;
    float m_lo = -1e30f, m_hi = -1e30f, l_lo = 0.f, l_hi = 0.f;

    const int row_lo = q0 + m0 + gr;
    const int row_hi = row_lo + 8;
    const int nkt = 2 * qb + 2;

    for (int kt = 0; kt < nkt; kt++) {
        int kv0 = kt * 64;
        __syncthreads();

        const float* Kbase = QKV + (size_t)(b * Tt + kv0) * QKVN + 1024 + kvh * HDim;
        const float* Vbase = Kbase + 256;
#pragma unroll
        for (int i = 0; i < 4; i++) {
            int fi = i * 256 + tid;
            int row = fi >> 4, c4 = (fi & 15) * 4;
            size_t g = (size_t)row * QKVN + c4;
            float4 kv = *(const float4*)(Kbase + g);
            float4 vv = *(const float4*)(Vbase + g);
            float* dk = &Ks[row * AST + c4];
            float* dv = &Vs[row * AST + c4];
            dk[0] = tf(kv.x); dk[1] = tf(kv.y); dk[2] = tf(kv.z); dk[3] = tf(kv.w);
            dv[0] = tf(vv.x); dv[1] = tf(vv.y); dv[2] = tf(vv.z); dv[3] = tf(vv.w);
        }
        __syncthreads();

        float s[8][4];
#pragma unroll
        for (int nt = 0; nt < 8; nt++)
#pragma unroll
            for (int i = 0; i < 4; i++) s[nt][i] = 0.f;

#pragma unroll
        for (int ks = 0; ks < 8; ks++) {
            uint32_t kf[4][4];
#pragma unroll
            for (int p = 0; p < 4; p++)
                ldmx4(kf[p], Ks_u + 4 * ((p * 16 + aro) * AST + ks * 8 + aco));
#pragma unroll
            for (int nt = 0; nt < 8; nt++) {
                int p = nt >> 1, hh = nt & 1;
                mma4(s[nt], qf[ks][0], qf[ks][2], qf[ks][1], qf[ks][3],
                     kf[p][2 * hh], kf[p][2 * hh + 1]);
            }
        }

        if (kv0 + 63 > q0) {
#pragma unroll
            for (int nt = 0; nt < 8; nt++) {
                int c0 = kv0 + nt * 8 + 2 * gc;
                if (c0 > row_lo)     s[nt][0] = -1e30f;
                if (c0 + 1 > row_lo) s[nt][1] = -1e30f;
                if (c0 > row_hi)     s[nt][2] = -1e30f;
                if (c0 + 1 > row_hi) s[nt][3] = -1e30f;
            }
        }

        float tlo = -1e30f, thi = -1e30f;
#pragma unroll
        for (int nt = 0; nt < 8; nt++) {
            tlo = fmaxf(tlo, fmaxf(s[nt][0], s[nt][1]));
            thi = fmaxf(thi, fmaxf(s[nt][2], s[nt][3]));
        }
        tlo = fmaxf(tlo, __shfl_xor_sync(0xffffffffu, tlo, 1));
        tlo = fmaxf(tlo, __shfl_xor_sync(0xffffffffu, tlo, 2));
        thi = fmaxf(thi, __shfl_xor_sync(0xffffffffu, thi, 1));
        thi = fmaxf(thi, __shfl_xor_sync(0xffffffffu, thi, 2));

        float mn_lo = fmaxf(m_lo, tlo);
        float mn_hi = fmaxf(m_hi, thi);
        float cor_lo = __expf(m_lo - mn_lo);
        float cor_hi = __expf(m_hi - mn_hi);
        m_lo = mn_lo; m_hi = mn_hi;
        l_lo *= cor_lo; l_hi *= cor_hi;
#pragma unroll
        for (int nt = 0; nt < 8; nt++) {
            o[nt][0] *= cor_lo; o[nt][1] *= cor_lo;
            o[nt][2] *= cor_hi; o[nt][3] *= cor_hi;
        }

        float* Ps = Qs;
#pragma unroll
        for (int nt = 0; nt < 8; nt++) {
            float p0 = __expf(s[nt][0] - m_lo);
            float p1 = __expf(s[nt][1] - m_lo);
            float p2 = __expf(s[nt][2] - m_hi);
            float p3 = __expf(s[nt][3] - m_hi);
            l_lo += p0 + p1;
            l_hi += p2 + p3;
            *(float2*)&Ps[(m0 + gr) * AST + nt * 8 + 2 * gc] =
                make_float2(tf(p0), tf(p1));
            *(float2*)&Ps[(m0 + 8 + gr) * AST + nt * 8 + 2 * gc] =
                make_float2(tf(p2), tf(p3));
        }
        __syncthreads();

#pragma unroll
        for (int ks = 0; ks < 8; ks++) {
            uint32_t pf[4];
            ldmx4(pf, Qs_u + 4 * ((m0 + aro) * AST + ks * 8 + aco));
#pragma unroll
            for (int nt = 0; nt < 8; nt++) {
                uint32_t b0 = __float_as_uint(Vs[(ks * 8 + gc) * AST + nt * 8 + gr]);
                uint32_t b1 = __float_as_uint(Vs[(ks * 8 + gc + 4) * AST + nt * 8 + gr]);
                mma4(o[nt], pf[0], pf[2], pf[1], pf[3], b0, b1);
            }
        }
    }

    l_lo += __shfl_xor_sync(0xffffffffu, l_lo, 1);
    l_lo += __shfl_xor_sync(0xffffffffu, l_lo, 2);
    l_hi += __shfl_xor_sync(0xffffffffu, l_hi, 1);
    l_hi += __shfl_xor_sync(0xffffffffu, l_hi, 2);
    float inv_lo = 1.f / l_lo;
    float inv_hi = 1.f / l_hi;

    float* Obase = Og + ((size_t)(b * Tt) * Hh + h) * HDim;
#pragma unroll
    for (int nt = 0; nt < 8; nt++) {
        int col = nt * 8 + 2 * gc;
        *(float2*)&Obase[(size_t)row_lo * (Hh * HDim) + col] =
            make_float2(tf(o[nt][0] * inv_lo), tf(o[nt][1] * inv_lo));
        *(float2*)&Obase[(size_t)row_hi * (Hh * HDim) + col] =
            make_float2(tf(o[nt][2] * inv_hi), tf(o[nt][3] * inv_hi));
    }
}

#define FLASH_SMEM ((128 + 64 + 64) * AST * 4)

// ============================================================
// launch
// ============================================================
extern "C" void kernel_launch(void* const* d_in, const int* in_sizes, int n_in,
                              void* d_out, int out_size)
{
    const float* x  = (const float*)d_in[0];
    const float* cs = (const float*)d_in[1];
    const float* sn = (const float*)d_in[2];
    const float* Wq = (const float*)d_in[3];
    const float* Wk = (const float*)d_in[4];
    const float* Wv = (const float*)d_in[5];
    const float* Wo = (const float*)d_in[6];
    float* out = (float*)d_out;

    float *Xtf, *QKVp, *Yp, *WqkvT, *WoT;
    cudaGetSymbolAddress((void**)&Xtf, g_Xtf);
    cudaGetSymbolAddress((void**)&QKVp, g_QKV);
    cudaGetSymbolAddress((void**)&Yp, g_Y);
    cudaGetSymbolAddress((void**)&WqkvT, g_WqkvT);
    cudaGetSymbolAddress((void**)&WoT, g_WoT);

    cudaFuncSetAttribute(gemm_mma,
                         cudaFuncAttributeMaxDynamicSharedMemorySize, GEMM_SMEM);
    cudaFuncSetAttribute(flash_attn_mma,
                         cudaFuncAttributeMaxDynamicSharedMemorySize, FLASH_SMEM);

    const int M = Bsz * Tt;  // 4096

    transpose_qkv<<<dim3(48, 32), dim3(32, 8)>>>(Wq, Wk, Wv, WqkvT);
    transpose_k<<<dim3(32, 32), dim3(32, 8)>>>(Wo, WoT, Cc, Cc);
    cvt_x<<<(M * Cc / 4) / 256, 256>>>(x, Xtf);

    gemm_mma<<<dim3(QKVN / 128, M / 128), 256, GEMM_SMEM>>>(Xtf, WqkvT, QKVp, M, QKVN, Cc);

    {
        int warps = M * (Hh + KVh);
        int threads = warps * 32;
        rope_rms<<<threads / 256, 256>>>(QKVp, cs, sn);
    }

    flash_attn_mma<<<dim3(Tt / 128, Hh, Bsz), 256, FLASH_SMEM>>>(QKVp, Yp);

    gemm_mma<<<dim3(Cc / 128, M / 128), 256, GEMM_SMEM>>>(Yp, WoT, out, M, Cc, Cc);
}

// round 8
// speedup vs baseline: 1.8055x; 1.8055x over previous
#include <cuda_runtime.h>
#include <cuda_fp16.h>
#include <math.h>
#include <stdint.h>

#define Bsz 2
#define Tt  2048
#define Cc  1024
#define Hh  16
#define KVh 4
#define HDim 64
#define QKVN 1536   // 1024 Q + 256 K + 256 V

// -------- scratch (static device globals; no allocation) --------
__device__ __half g_Xh[Bsz * Tt * Cc];          // x in fp16
__device__ float  g_QKV[Bsz * Tt * QKVN];       // fused Q|K|V rows (fp32)
__device__ __half g_Yh[Bsz * Tt * Hh * HDim];   // attention out (fp16)
__device__ __half g_WqkvTh[QKVN * Cc];          // transposed fp16
__device__ __half g_WoTh[Cc * Cc];              // transposed fp16

// fp16 mma: D(f32) += A(f16) B(f16), m16n8k16
__device__ __forceinline__ void mma16816(float* c,
    uint32_t a0, uint32_t a1, uint32_t a2, uint32_t a3,
    uint32_t b0, uint32_t b1) {
    asm volatile(
        "mma.sync.aligned.m16n8k16.row.col.f32.f16.f16.f32 "
        "{%0,%1,%2,%3}, {%4,%5,%6,%7}, {%8,%9}, {%0,%1,%2,%3};"
        : "+f"(c[0]), "+f"(c[1]), "+f"(c[2]), "+f"(c[3])
        : "r"(a0), "r"(a1), "r"(a2), "r"(a3), "r"(b0), "r"(b1));
}

__device__ __forceinline__ void ldmx4(uint32_t* r, uint32_t saddr) {
    asm volatile("ldmatrix.sync.aligned.m8n8.x4.shared.b16 {%0,%1,%2,%3}, [%4];"
        : "=r"(r[0]), "=r"(r[1]), "=r"(r[2]), "=r"(r[3]) : "r"(saddr));
}
__device__ __forceinline__ void ldmx4t(uint32_t* r, uint32_t saddr) {
    asm volatile("ldmatrix.sync.aligned.m8n8.x4.trans.shared.b16 {%0,%1,%2,%3}, [%4];"
        : "=r"(r[0]), "=r"(r[1]), "=r"(r[2]), "=r"(r[3]) : "r"(saddr));
}

__device__ __forceinline__ void cpa16(void* s, const void* g) {
    uint32_t sa = (uint32_t)__cvta_generic_to_shared(s);
    asm volatile("cp.async.ca.shared.global [%0], [%1], 16;" :: "r"(sa), "l"(g));
}
#define CP_COMMIT() asm volatile("cp.async.commit_group;" ::: "memory")
#define CP_WAIT(n)  asm volatile("cp.async.wait_group %0;" :: "n"(n) : "memory")

// ============================================================
// x -> fp16
// ============================================================
__global__ __launch_bounds__(256) void cvt_x(
    const float* __restrict__ in, __half* __restrict__ out)
{
    int i = blockIdx.x * blockDim.x + threadIdx.x;
    float4 v = *(const float4*)(in + (size_t)i * 4);
    __half2* o = (__half2*)(out + (size_t)i * 4);
    o[0] = __floats2half2_rn(v.x, v.y);
    o[1] = __floats2half2_rn(v.z, v.w);
}

// ============================================================
// Fused QKV weight transpose -> fp16
// ============================================================
__global__ __launch_bounds__(256) void transpose_qkv(
    const float* __restrict__ Wq, const float* __restrict__ Wk,
    const float* __restrict__ Wv, __half* __restrict__ out)
{
    __shared__ float tile[32][33];
    int nblk = blockIdx.x;
    int k0 = blockIdx.y * 32;
    int tx = threadIdx.x, ty = threadIdx.y;

    const float* src;
    int N, nloc;
    if (nblk < 32)      { src = Wq; N = 1024; nloc = nblk * 32; }
    else if (nblk < 40) { src = Wk; N = 256;  nloc = (nblk - 32) * 32; }
    else                { src = Wv; N = 256;  nloc = (nblk - 40) * 32; }

#pragma unroll
    for (int i = 0; i < 32; i += 8)
        tile[ty + i][tx] = src[(size_t)(k0 + ty + i) * N + nloc + tx];
    __syncthreads();
#pragma unroll
    for (int i = 0; i < 32; i += 8)
        out[(size_t)(nblk * 32 + ty + i) * Cc + k0 + tx] = __float2half(tile[tx][ty + i]);
}

__global__ __launch_bounds__(256) void transpose_k(
    const float* __restrict__ in, __half* __restrict__ out, int K, int N)
{
    __shared__ float tile[32][33];
    int k0 = blockIdx.y * 32, n0 = blockIdx.x * 32;
    int tx = threadIdx.x, ty = threadIdx.y;
#pragma unroll
    for (int i = 0; i < 32; i += 8)
        tile[ty + i][tx] = in[(size_t)(k0 + ty + i) * N + n0 + tx];
    __syncthreads();
#pragma unroll
    for (int i = 0; i < 32; i += 8)
        out[(size_t)(n0 + ty + i) * K + k0 + tx] = __float2half(tile[tx][ty + i]);
}

// ============================================================
// fp16 mma.sync GEMM: C[M,N](f32) = A[M,K] @ BT[N,K]^T
// 128x128 tile, 256 thr (8 warps 2m x 4n), K-chunk 32,
// 3-stage cp.async, ldmatrix frags. Stride 40 halfs (pad 8).
// ============================================================
#define SMH 40                         // halfs per row
#define STAGE_H (2 * 128 * SMH)        // halfs per stage
#define GEMM_SMEM (3 * STAGE_H * 2)    // 61440 bytes

__global__ __launch_bounds__(256, 2) void gemm_mma(
    const __half* __restrict__ A, const __half* __restrict__ BT,
    float* __restrict__ C, int M, int N, int K)
{
    extern __shared__ __half sh[];

    int tid = threadIdx.x;
    int wid = tid >> 5;
    int lane = tid & 31;
    int gr = lane >> 2;
    int gc = lane & 3;
    int bm = blockIdx.y * 128, bn = blockIdx.x * 128;
    int m0 = (wid & 1) * 64;
    int n0 = (wid >> 1) * 32;

    // ldmatrix lane offsets: A-type and B-type
    const int aro = ((lane & 8) ? 8 : 0) + (lane & 7);
    const int aco = (lane & 16) ? 8 : 0;
    const int bro = ((lane & 16) ? 8 : 0) + (lane & 7);
    const int bco = (lane & 8) ? 8 : 0;

    const int crow = tid >> 2;        // 0..63
    const int ccol = (tid & 3) * 8;   // half col 0..24

    const uint32_t sh_u32 = (uint32_t)__cvta_generic_to_shared(sh);

    float acc[4][4][4];
#pragma unroll
    for (int mt = 0; mt < 4; mt++)
#pragma unroll
        for (int nt = 0; nt < 4; nt++)
#pragma unroll
            for (int i = 0; i < 4; i++) acc[mt][nt][i] = 0.f;

    auto issue = [&](int s, int kc) {
        __half* As = sh + s * STAGE_H;
        __half* Bs = As + 128 * SMH;
#pragma unroll
        for (int i = 0; i < 2; i++) {
            int row = i * 64 + crow;
            cpa16(&As[row * SMH + ccol], A  + (size_t)(bm + row) * K + kc + ccol);
            cpa16(&Bs[row * SMH + ccol], BT + (size_t)(bn + row) * K + kc + ccol);
        }
        CP_COMMIT();
    };

    const int NCH = K / 32;
    issue(0, 0);
    issue(1, 32);

    int s = 0;
    for (int c = 0; c < NCH; c++) {
        if (c == NCH - 1) { CP_WAIT(0); } else { CP_WAIT(1); }
        __syncthreads();
        if (c + 2 < NCH) {
            int s2 = s + 2; if (s2 >= 3) s2 -= 3;
            issue(s2, (c + 2) * 32);
        }

        uint32_t As_u = sh_u32 + s * STAGE_H * 2;
        uint32_t Bs_u = As_u + 128 * SMH * 2;
#pragma unroll
        for (int ks = 0; ks < 2; ks++) {
            int k0 = ks * 16;
            uint32_t am[4][4], bmx[2][4];
#pragma unroll
            for (int mt = 0; mt < 4; mt++)
                ldmx4(am[mt], As_u + 2 * ((m0 + mt * 16 + aro) * SMH + k0 + aco));
#pragma unroll
            for (int p = 0; p < 2; p++)
                ldmx4(bmx[p], Bs_u + 2 * ((n0 + p * 16 + bro) * SMH + k0 + bco));
#pragma unroll
            for (int mt = 0; mt < 4; mt++)
#pragma unroll
                for (int nt = 0; nt < 4; nt++) {
                    int p = nt >> 1, h = nt & 1;
                    mma16816(acc[mt][nt],
                             am[mt][0], am[mt][1], am[mt][2], am[mt][3],
                             bmx[p][2 * h], bmx[p][2 * h + 1]);
                }
        }
        if (++s >= 3) s -= 3;
    }

#pragma unroll
    for (int mt = 0; mt < 4; mt++) {
#pragma unroll
        for (int nt = 0; nt < 4; nt++) {
            int row = bm + m0 + mt * 16 + gr;
            int col = bn + n0 + nt * 8 + 2 * gc;
            *(float2*)&C[(size_t)row * N + col] =
                make_float2(acc[mt][nt][0], acc[mt][nt][1]);
            *(float2*)&C[(size_t)(row + 8) * N + col] =
                make_float2(acc[mt][nt][2], acc[mt][nt][3]);
        }
    }
}

// ============================================================
// RoPE + RMSNorm over fused QKV buffer (fp32, stride QKVN).
// ============================================================
__global__ __launch_bounds__(256) void rope_rms(
    float* __restrict__ QKV,
    const float* __restrict__ cosp, const float* __restrict__ sinp)
{
    int gw = (blockIdx.x * blockDim.x + threadIdx.x) >> 5;
    int lane = threadIdx.x & 31;
    const int total_q = Bsz * Tt * Hh;

    float* p;
    int t;
    if (gw < total_q) {
        int bt = gw / Hh, h = gw % Hh;
        t = bt % Tt;
        p = QKV + (size_t)bt * QKVN + h * HDim;
    } else {
        int g = gw - total_q;
        int bt = g / KVh, kv = g % KVh;
        t = bt % Tt;
        p = QKV + (size_t)bt * QKVN + 1024 + kv * HDim;
    }

    float c = cosp[t * (HDim / 2) + lane];
    float s = sinp[t * (HDim / 2) + lane];
    float x1 = p[lane];
    float x2 = p[lane + 32];
    float o1 = x1 * c + x2 * s;
    float o2 = -x1 * s + x2 * c;

    float ss = o1 * o1 + o2 * o2;
#pragma unroll
    for (int off = 16; off > 0; off >>= 1)
        ss += __shfl_xor_sync(0xffffffffu, ss, off);

    float inv = rsqrtf(ss * (1.0f / HDim) + 1e-6f);
    p[lane]      = o1 * inv;
    p[lane + 32] = o2 * inv;
}

// ============================================================
// fp16 mma.sync causal GQA flash attention.
// grid = (T/128, H, B), 256 threads (8 warps x 16 q-rows).
// Q/P 128x72, K 64x72, V 64x72 halfs. V via ldmatrix.trans.
// ============================================================
#define AST 72   // halfs per row; 72*2=144B -> 4-bank row step, conflict-free

__global__ __launch_bounds__(256) void flash_attn_mma(
    const float* __restrict__ QKV, __half* __restrict__ Og)
{
    __shared__ __half Qs[128 * AST];   // also P
    __shared__ __half Ks[64 * AST];
    __shared__ __half Vs[64 * AST];

    int qb = blockIdx.x, h = blockIdx.y, b = blockIdx.z;
    int q0 = qb * 128;
    int kvh = h >> 2;
    int tid = threadIdx.x, wid = tid >> 5, lane = tid & 31;
    int gr = lane >> 2, gc = lane & 3;
    int m0 = wid * 16;
    const int aro = ((lane & 8) ? 8 : 0) + (lane & 7);
    const int aco = (lane & 16) ? 8 : 0;
    const int bro = ((lane & 16) ? 8 : 0) + (lane & 7);
    const int bco = (lane & 8) ? 8 : 0;

    const uint32_t Qs_u = (uint32_t)__cvta_generic_to_shared(Qs);
    const uint32_t Ks_u = (uint32_t)__cvta_generic_to_shared(Ks);
    const uint32_t Vs_u = (uint32_t)__cvta_generic_to_shared(Vs);

    // ---- stage Q (scaled 1/8) ----
    const float* Qbase = QKV + (size_t)(b * Tt + q0) * QKVN + h * HDim;
#pragma unroll
    for (int i = 0; i < 8; i++) {
        int fi = i * 256 + tid;
        int row = fi >> 4, c4 = (fi & 15) * 4;
        float4 v = *(const float4*)(Qbase + (size_t)row * QKVN + c4);
        __half2* d = (__half2*)&Qs[row * AST + c4];
        d[0] = __floats2half2_rn(v.x * 0.125f, v.y * 0.125f);
        d[1] = __floats2half2_rn(v.z * 0.125f, v.w * 0.125f);
    }
    __syncthreads();

    uint32_t qf[4][4];
#pragma unroll
    for (int ks = 0; ks < 4; ks++)
        ldmx4(qf[ks], Qs_u + 2 * ((m0 + aro) * AST + ks * 16 + aco));
    __syncthreads();

    float o[8][4];
#pragma unroll
    for (int nt = 0; nt < 8; nt++)
#pragma unroll
        for (int i = 0; i < 4; i++) o[nt][i] = 0.f;
    float m_lo = -1e30f, m_hi = -1e30f, l_lo = 0.f, l_hi = 0.f;

    const int row_lo = q0 + m0 + gr;
    const int row_hi = row_lo + 8;
    const int nkt = 2 * qb + 2;

    for (int kt = 0; kt < nkt; kt++) {
        int kv0 = kt * 64;
        __syncthreads();

        const float* Kbase = QKV + (size_t)(b * Tt + kv0) * QKVN + 1024 + kvh * HDim;
        const float* Vbase = Kbase + 256;
#pragma unroll
        for (int i = 0; i < 4; i++) {
            int fi = i * 256 + tid;
            int row = fi >> 4, c4 = (fi & 15) * 4;
            size_t g = (size_t)row * QKVN + c4;
            float4 kv = *(const float4*)(Kbase + g);
            float4 vv = *(const float4*)(Vbase + g);
            __half2* dk = (__half2*)&Ks[row * AST + c4];
            __half2* dv = (__half2*)&Vs[row * AST + c4];
            dk[0] = __floats2half2_rn(kv.x, kv.y);
            dk[1] = __floats2half2_rn(kv.z, kv.w);
            dv[0] = __floats2half2_rn(vv.x, vv.y);
            dv[1] = __floats2half2_rn(vv.z, vv.w);
        }
        __syncthreads();

        // ---- S = Q K^T ----
        float s[8][4];
#pragma unroll
        for (int nt = 0; nt < 8; nt++)
#pragma unroll
            for (int i = 0; i < 4; i++) s[nt][i] = 0.f;

#pragma unroll
        for (int ks = 0; ks < 4; ks++) {
            uint32_t kf[4][4];
#pragma unroll
            for (int p = 0; p < 4; p++)
                ldmx4(kf[p], Ks_u + 2 * ((p * 16 + bro) * AST + ks * 16 + bco));
#pragma unroll
            for (int nt = 0; nt < 8; nt++) {
                int p = nt >> 1, hh = nt & 1;
                mma16816(s[nt], qf[ks][0], qf[ks][1], qf[ks][2], qf[ks][3],
                         kf[p][2 * hh], kf[p][2 * hh + 1]);
            }
        }

        if (kv0 + 63 > q0) {
#pragma unroll
            for (int nt = 0; nt < 8; nt++) {
                int c0 = kv0 + nt * 8 + 2 * gc;
                if (c0 > row_lo)     s[nt][0] = -1e30f;
                if (c0 + 1 > row_lo) s[nt][1] = -1e30f;
                if (c0 > row_hi)     s[nt][2] = -1e30f;
                if (c0 + 1 > row_hi) s[nt][3] = -1e30f;
            }
        }

        float tlo = -1e30f, thi = -1e30f;
#pragma unroll
        for (int nt = 0; nt < 8; nt++) {
            tlo = fmaxf(tlo, fmaxf(s[nt][0], s[nt][1]));
            thi = fmaxf(thi, fmaxf(s[nt][2], s[nt][3]));
        }
        tlo = fmaxf(tlo, __shfl_xor_sync(0xffffffffu, tlo, 1));
        tlo = fmaxf(tlo, __shfl_xor_sync(0xffffffffu, tlo, 2));
        thi = fmaxf(thi, __shfl_xor_sync(0xffffffffu, thi, 1));
        thi = fmaxf(thi, __shfl_xor_sync(0xffffffffu, thi, 2));

        float mn_lo = fmaxf(m_lo, tlo);
        float mn_hi = fmaxf(m_hi, thi);
        float cor_lo = __expf(m_lo - mn_lo);
        float cor_hi = __expf(m_hi - mn_hi);
        m_lo = mn_lo; m_hi = mn_hi;
        l_lo *= cor_lo; l_hi *= cor_hi;
#pragma unroll
        for (int nt = 0; nt < 8; nt++) {
            o[nt][0] *= cor_lo; o[nt][1] *= cor_lo;
            o[nt][2] *= cor_hi; o[nt][3] *= cor_hi;
        }

        // ---- P = exp(S - m) -> smem (fp16) ----
        __half* Ps = Qs;
#pragma unroll
        for (int nt = 0; nt < 8; nt++) {
            float p0 = __expf(s[nt][0] - m_lo);
            float p1 = __expf(s[nt][1] - m_lo);
            float p2 = __expf(s[nt][2] - m_hi);
            float p3 = __expf(s[nt][3] - m_hi);
            l_lo += p0 + p1;
            l_hi += p2 + p3;
            *(__half2*)&Ps[(m0 + gr) * AST + nt * 8 + 2 * gc] =
                __floats2half2_rn(p0, p1);
            *(__half2*)&Ps[(m0 + 8 + gr) * AST + nt * 8 + 2 * gc] =
                __floats2half2_rn(p2, p3);
        }
        __syncthreads();

        // ---- O += P V ----
#pragma unroll
        for (int ks = 0; ks < 4; ks++) {
            uint32_t pf[4], vf[4][4];
            ldmx4(pf, Qs_u + 2 * ((m0 + aro) * AST + ks * 16 + aco));
#pragma unroll
            for (int p = 0; p < 4; p++)
                ldmx4t(vf[p], Vs_u + 2 * ((ks * 16 + aro) * AST + p * 16 + aco));
#pragma unroll
            for (int nt = 0; nt < 8; nt++) {
                int p = nt >> 1, hh = nt & 1;
                mma16816(o[nt], pf[0], pf[1], pf[2], pf[3],
                         vf[p][2 * hh], vf[p][2 * hh + 1]);
            }
        }
    }

    l_lo += __shfl_xor_sync(0xffffffffu, l_lo, 1);
    l_lo += __shfl_xor_sync(0xffffffffu, l_lo, 2);
    l_hi += __shfl_xor_sync(0xffffffffu, l_hi, 1);
    l_hi += __shfl_xor_sync(0xffffffffu, l_hi, 2);
    float inv_lo = 1.f / l_lo;
    float inv_hi = 1.f / l_hi;

    __half* Obase = Og + ((size_t)(b * Tt) * Hh + h) * HDim;
#pragma unroll
    for (int nt = 0; nt < 8; nt++) {
        int col = nt * 8 + 2 * gc;
        *(__half2*)&Obase[(size_t)row_lo * (Hh * HDim) + col] =
            __floats2half2_rn(o[nt][0] * inv_lo, o[nt][1] * inv_lo);
        *(__half2*)&Obase[(size_t)row_hi * (Hh * HDim) + col] =
            __floats2half2_rn(o[nt][2] * inv_hi, o[nt][3] * inv_hi);
    }
}

// ============================================================
// launch
// ============================================================
extern "C" void kernel_launch(void* const* d_in, const int* in_sizes, int n_in,
                              void* d_out, int out_size)
{
    const float* x  = (const float*)d_in[0];
    const float* cs = (const float*)d_in[1];
    const float* sn = (const float*)d_in[2];
    const float* Wq = (const float*)d_in[3];
    const float* Wk = (const float*)d_in[4];
    const float* Wv = (const float*)d_in[5];
    const float* Wo = (const float*)d_in[6];
    float* out = (float*)d_out;

    __half *Xh, *Yh, *WqkvTh, *WoTh;
    float *QKVp;
    cudaGetSymbolAddress((void**)&Xh, g_Xh);
    cudaGetSymbolAddress((void**)&QKVp, g_QKV);
    cudaGetSymbolAddress((void**)&Yh, g_Yh);
    cudaGetSymbolAddress((void**)&WqkvTh, g_WqkvTh);
    cudaGetSymbolAddress((void**)&WoTh, g_WoTh);

    cudaFuncSetAttribute(gemm_mma,
                         cudaFuncAttributeMaxDynamicSharedMemorySize, GEMM_SMEM);

    const int M = Bsz * Tt;  // 4096

    transpose_qkv<<<dim3(48, 32), dim3(32, 8)>>>(Wq, Wk, Wv, WqkvTh);
    transpose_k<<<dim3(32, 32), dim3(32, 8)>>>(Wo, WoTh, Cc, Cc);
    cvt_x<<<(M * Cc / 4) / 256, 256>>>(x, Xh);

    // fused QKV projection
    gemm_mma<<<dim3(QKVN / 128, M / 128), 256, GEMM_SMEM>>>(Xh, WqkvTh, QKVp, M, QKVN, Cc);

    // RoPE + RMSNorm on Q and K slices
    {
        int warps = M * (Hh + KVh);
        int threads = warps * 32;
        rope_rms<<<threads / 256, 256>>>(QKVp, cs, sn);
    }

    // causal GQA flash attention (fp16 output)
    flash_attn_mma<<<dim3(Tt / 128, Hh, Bsz), 256>>>(QKVp, Yh);

    // output projection
    gemm_mma<<<dim3(Cc / 128, M / 128), 256, GEMM_SMEM>>>(Yh, WoTh, out, M, Cc, Cc);
}

// round 9
// speedup vs baseline: 2.0619x; 1.1420x over previous
#include <cuda_runtime.h>
#include <cuda_fp16.h>
#include <math.h>
#include <stdint.h>

#define Bsz 2
#define Tt  2048
#define Cc  1024
#define Hh  16
#define KVh 4
#define HDim 64
#define QKVN 1536   // 1024 Q + 256 K + 256 V
#define QSCALE 0.1803368801111204f   // 0.125 * log2(e)

// -------- scratch (static device globals; no allocation) --------
__device__ __align__(256) __half g_Xh[Bsz * Tt * Cc];
__device__ __align__(256) __half g_QKVh[Bsz * Tt * QKVN];   // fp16, Q pre-scaled
__device__ __align__(256) __half g_Yh[Bsz * Tt * Hh * HDim];
__device__ __align__(256) __half g_WqkvTh[QKVN * Cc];
__device__ __align__(256) __half g_WoTh[Cc * Cc];

__device__ __forceinline__ void mma16816(float* c,
    uint32_t a0, uint32_t a1, uint32_t a2, uint32_t a3,
    uint32_t b0, uint32_t b1) {
    asm volatile(
        "mma.sync.aligned.m16n8k16.row.col.f32.f16.f16.f32 "
        "{%0,%1,%2,%3}, {%4,%5,%6,%7}, {%8,%9}, {%0,%1,%2,%3};"
        : "+f"(c[0]), "+f"(c[1]), "+f"(c[2]), "+f"(c[3])
        : "r"(a0), "r"(a1), "r"(a2), "r"(a3), "r"(b0), "r"(b1));
}

__device__ __forceinline__ void ldmx4(uint32_t* r, uint32_t saddr) {
    asm volatile("ldmatrix.sync.aligned.m8n8.x4.shared.b16 {%0,%1,%2,%3}, [%4];"
        : "=r"(r[0]), "=r"(r[1]), "=r"(r[2]), "=r"(r[3]) : "r"(saddr));
}
__device__ __forceinline__ void ldmx4t(uint32_t* r, uint32_t saddr) {
    asm volatile("ldmatrix.sync.aligned.m8n8.x4.trans.shared.b16 {%0,%1,%2,%3}, [%4];"
        : "=r"(r[0]), "=r"(r[1]), "=r"(r[2]), "=r"(r[3]) : "r"(saddr));
}

__device__ __forceinline__ void cpa16(void* s, const void* g) {
    uint32_t sa = (uint32_t)__cvta_generic_to_shared(s);
    asm volatile("cp.async.ca.shared.global [%0], [%1], 16;" :: "r"(sa), "l"(g));
}
#define CP_COMMIT() asm volatile("cp.async.commit_group;" ::: "memory")
#define CP_WAIT(n)  asm volatile("cp.async.wait_group %0;" :: "n"(n) : "memory")

__device__ __forceinline__ float ex2f(float x) {
    float y;
    asm("ex2.approx.ftz.f32 %0, %1;" : "=f"(y) : "f"(x));
    return y;
}

// ============================================================
// x -> fp16
// ============================================================
__global__ __launch_bounds__(256) void cvt_x(
    const float* __restrict__ in, __half* __restrict__ out)
{
    int i = blockIdx.x * blockDim.x + threadIdx.x;
    float4 v = *(const float4*)(in + (size_t)i * 4);
    __half2* o = (__half2*)(out + (size_t)i * 4);
    o[0] = __floats2half2_rn(v.x, v.y);
    o[1] = __floats2half2_rn(v.z, v.w);
}

// ============================================================
// Fused QKV weight transpose -> fp16
// ============================================================
__global__ __launch_bounds__(256) void transpose_qkv(
    const float* __restrict__ Wq, const float* __restrict__ Wk,
    const float* __restrict__ Wv, __half* __restrict__ out)
{
    __shared__ float tile[32][33];
    int nblk = blockIdx.x;
    int k0 = blockIdx.y * 32;
    int tx = threadIdx.x, ty = threadIdx.y;

    const float* src;
    int N, nloc;
    if (nblk < 32)      { src = Wq; N = 1024; nloc = nblk * 32; }
    else if (nblk < 40) { src = Wk; N = 256;  nloc = (nblk - 32) * 32; }
    else                { src = Wv; N = 256;  nloc = (nblk - 40) * 32; }

#pragma unroll
    for (int i = 0; i < 32; i += 8)
        tile[ty + i][tx] = src[(size_t)(k0 + ty + i) * N + nloc + tx];
    __syncthreads();
#pragma unroll
    for (int i = 0; i < 32; i += 8)
        out[(size_t)(nblk * 32 + ty + i) * Cc + k0 + tx] = __float2half(tile[tx][ty + i]);
}

__global__ __launch_bounds__(256) void transpose_k(
    const float* __restrict__ in, __half* __restrict__ out, int K, int N)
{
    __shared__ float tile[32][33];
    int k0 = blockIdx.y * 32, n0 = blockIdx.x * 32;
    int tx = threadIdx.x, ty = threadIdx.y;
#pragma unroll
    for (int i = 0; i < 32; i += 8)
        tile[ty + i][tx] = in[(size_t)(k0 + ty + i) * N + n0 + tx];
    __syncthreads();
#pragma unroll
    for (int i = 0; i < 32; i += 8)
        out[(size_t)(n0 + ty + i) * K + k0 + tx] = __float2half(tile[tx][ty + i]);
}

// ============================================================
// shared GEMM mainloop pieces
// ============================================================
#define SMH 40
#define STAGE_H (2 * 128 * SMH)
#define GEMM_SMEM (3 * STAGE_H * 2)          // 61440
#define QKV_SMEM  (128 * 132 * 4)            // 67584 (>= GEMM_SMEM)

// ============================================================
// QKV GEMM with fused rope+rms epilogue -> fp16 QKVh.
// grid (12, 32). N-tiles: 0-7 Q (scaled), 8-9 K, 10-11 V.
// ============================================================
__global__ __launch_bounds__(256, 2) void gemm_qkv(
    const __half* __restrict__ A, const __half* __restrict__ BT,
    __half* __restrict__ Og,
    const float* __restrict__ cosp, const float* __restrict__ sinp)
{
    extern __shared__ __half sh[];
    const int M_K = Cc;   // K dim = 1024

    int tid = threadIdx.x;
    int wid = tid >> 5;
    int lane = tid & 31;
    int gr = lane >> 2;
    int gc = lane & 3;
    int bm = blockIdx.y * 128, bn = blockIdx.x * 128;
    int m0 = (wid & 1) * 64;
    int n0 = (wid >> 1) * 32;

    const int aro = ((lane & 8) ? 8 : 0) + (lane & 7);
    const int aco = (lane & 16) ? 8 : 0;
    const int bro = ((lane & 16) ? 8 : 0) + (lane & 7);
    const int bco = (lane & 8) ? 8 : 0;

    const int crow = tid >> 2;
    const int ccol = (tid & 3) * 8;

    const uint32_t sh_u32 = (uint32_t)__cvta_generic_to_shared(sh);

    float acc[4][4][4];
#pragma unroll
    for (int mt = 0; mt < 4; mt++)
#pragma unroll
        for (int nt = 0; nt < 4; nt++)
#pragma unroll
            for (int i = 0; i < 4; i++) acc[mt][nt][i] = 0.f;

    auto issue = [&](int s, int kc) {
        __half* As = sh + s * STAGE_H;
        __half* Bs = As + 128 * SMH;
#pragma unroll
        for (int i = 0; i < 2; i++) {
            int row = i * 64 + crow;
            cpa16(&As[row * SMH + ccol], A  + (size_t)(bm + row) * M_K + kc + ccol);
            cpa16(&Bs[row * SMH + ccol], BT + (size_t)(bn + row) * M_K + kc + ccol);
        }
        CP_COMMIT();
    };

    const int NCH = M_K / 32;
    issue(0, 0);
    issue(1, 32);

    int s = 0;
    for (int c = 0; c < NCH; c++) {
        if (c == NCH - 1) { CP_WAIT(0); } else { CP_WAIT(1); }
        __syncthreads();
        if (c + 2 < NCH) {
            int s2 = s + 2; if (s2 >= 3) s2 -= 3;
            issue(s2, (c + 2) * 32);
        }

        uint32_t As_u = sh_u32 + s * STAGE_H * 2;
        uint32_t Bs_u = As_u + 128 * SMH * 2;
#pragma unroll
        for (int ks = 0; ks < 2; ks++) {
            int k0 = ks * 16;
            uint32_t am[4][4], bmx[2][4];
#pragma unroll
            for (int mt = 0; mt < 4; mt++)
                ldmx4(am[mt], As_u + 2 * ((m0 + mt * 16 + aro) * SMH + k0 + aco));
#pragma unroll
            for (int p = 0; p < 2; p++)
                ldmx4(bmx[p], Bs_u + 2 * ((n0 + p * 16 + bro) * SMH + k0 + bco));
#pragma unroll
            for (int mt = 0; mt < 4; mt++)
#pragma unroll
                for (int nt = 0; nt < 4; nt++) {
                    int p = nt >> 1, h = nt & 1;
                    mma16816(acc[mt][nt],
                             am[mt][0], am[mt][1], am[mt][2], am[mt][3],
                             bmx[p][2 * h], bmx[p][2 * h + 1]);
                }
        }
        if (++s >= 3) s -= 3;
    }

    int ntile = blockIdx.x;
    if (ntile >= 10) {
        // ---- V: plain fp16 store ----
#pragma unroll
        for (int mt = 0; mt < 4; mt++)
#pragma unroll
            for (int nt = 0; nt < 4; nt++) {
                int row = bm + m0 + mt * 16 + gr;
                int col = bn + n0 + nt * 8 + 2 * gc;
                *(__half2*)&Og[(size_t)row * QKVN + col] =
                    __floats2half2_rn(acc[mt][nt][0], acc[mt][nt][1]);
                *(__half2*)&Og[(size_t)(row + 8) * QKVN + col] =
                    __floats2half2_rn(acc[mt][nt][2], acc[mt][nt][3]);
            }
        return;
    }

    // ---- Q/K: stage to smem (fp32), rope+rms per (row, head) ----
    __syncthreads();   // all warps done reading pipeline smem
    float* St = (float*)sh;
#pragma unroll
    for (int mt = 0; mt < 4; mt++)
#pragma unroll
        for (int nt = 0; nt < 4; nt++) {
            int r = m0 + mt * 16 + gr;
            int ccl = n0 + nt * 8 + 2 * gc;
            *(float2*)&St[r * 132 + ccl] =
                make_float2(acc[mt][nt][0], acc[mt][nt][1]);
            *(float2*)&St[(r + 8) * 132 + ccl] =
                make_float2(acc[mt][nt][2], acc[mt][nt][3]);
        }
    __syncthreads();

    float scl = (ntile < 8) ? QSCALE : 1.0f;
    for (int task = wid; task < 256; task += 8) {
        int row = task >> 1;
        int hh = task & 1;
        int t = (bm + row) & (Tt - 1);
        float cv = cosp[t * 32 + lane];
        float sv = sinp[t * 32 + lane];
        float x1 = St[row * 132 + hh * 64 + lane];
        float x2 = St[row * 132 + hh * 64 + lane + 32];
        float o1 = x1 * cv + x2 * sv;
        float o2 = -x1 * sv + x2 * cv;

        float ss = o1 * o1 + o2 * o2;
#pragma unroll
        for (int off = 16; off > 0; off >>= 1)
            ss += __shfl_xor_sync(0xffffffffu, ss, off);
        float inv = rsqrtf(ss * (1.0f / HDim) + 1e-6f) * scl;

        size_t gbase = (size_t)(bm + row) * QKVN + bn + hh * 64 + lane;
        Og[gbase]      = __float2half(o1 * inv);
        Og[gbase + 32] = __float2half(o2 * inv);
    }
}

// ============================================================
// plain fp16 GEMM (Wo): C fp32
// ============================================================
__global__ __launch_bounds__(256, 2) void gemm_mma(
    const __half* __restrict__ A, const __half* __restrict__ BT,
    float* __restrict__ C, int M, int N, int K)
{
    extern __shared__ __half sh[];

    int tid = threadIdx.x;
    int wid = tid >> 5;
    int lane = tid & 31;
    int gr = lane >> 2;
    int gc = lane & 3;
    int bm = blockIdx.y * 128, bn = blockIdx.x * 128;
    int m0 = (wid & 1) * 64;
    int n0 = (wid >> 1) * 32;

    const int aro = ((lane & 8) ? 8 : 0) + (lane & 7);
    const int aco = (lane & 16) ? 8 : 0;
    const int bro = ((lane & 16) ? 8 : 0) + (lane & 7);
    const int bco = (lane & 8) ? 8 : 0;

    const int crow = tid >> 2;
    const int ccol = (tid & 3) * 8;

    const uint32_t sh_u32 = (uint32_t)__cvta_generic_to_shared(sh);

    float acc[4][4][4];
#pragma unroll
    for (int mt = 0; mt < 4; mt++)
#pragma unroll
        for (int nt = 0; nt < 4; nt++)
#pragma unroll
            for (int i = 0; i < 4; i++) acc[mt][nt][i] = 0.f;

    auto issue = [&](int s, int kc) {
        __half* As = sh + s * STAGE_H;
        __half* Bs = As + 128 * SMH;
#pragma unroll
        for (int i = 0; i < 2; i++) {
            int row = i * 64 + crow;
            cpa16(&As[row * SMH + ccol], A  + (size_t)(bm + row) * K + kc + ccol);
            cpa16(&Bs[row * SMH + ccol], BT + (size_t)(bn + row) * K + kc + ccol);
        }
        CP_COMMIT();
    };

    const int NCH = K / 32;
    issue(0, 0);
    issue(1, 32);

    int s = 0;
    for (int c = 0; c < NCH; c++) {
        if (c == NCH - 1) { CP_WAIT(0); } else { CP_WAIT(1); }
        __syncthreads();
        if (c + 2 < NCH) {
            int s2 = s + 2; if (s2 >= 3) s2 -= 3;
            issue(s2, (c + 2) * 32);
        }

        uint32_t As_u = sh_u32 + s * STAGE_H * 2;
        uint32_t Bs_u = As_u + 128 * SMH * 2;
#pragma unroll
        for (int ks = 0; ks < 2; ks++) {
            int k0 = ks * 16;
            uint32_t am[4][4], bmx[2][4];
#pragma unroll
            for (int mt = 0; mt < 4; mt++)
                ldmx4(am[mt], As_u + 2 * ((m0 + mt * 16 + aro) * SMH + k0 + aco));
#pragma unroll
            for (int p = 0; p < 2; p++)
                ldmx4(bmx[p], Bs_u + 2 * ((n0 + p * 16 + bro) * SMH + k0 + bco));
#pragma unroll
            for (int mt = 0; mt < 4; mt++)
#pragma unroll
                for (int nt = 0; nt < 4; nt++) {
                    int p = nt >> 1, h = nt & 1;
                    mma16816(acc[mt][nt],
                             am[mt][0], am[mt][1], am[mt][2], am[mt][3],
                             bmx[p][2 * h], bmx[p][2 * h + 1]);
                }
        }
        if (++s >= 3) s -= 3;
    }

#pragma unroll
    for (int mt = 0; mt < 4; mt++) {
#pragma unroll
        for (int nt = 0; nt < 4; nt++) {
            int row = bm + m0 + mt * 16 + gr;
            int col = bn + n0 + nt * 8 + 2 * gc;
            *(float2*)&C[(size_t)row * N + col] =
                make_float2(acc[mt][nt][0], acc[mt][nt][1]);
            *(float2*)&C[(size_t)(row + 8) * N + col] =
                make_float2(acc[mt][nt][2], acc[mt][nt][3]);
        }
    }
}

// ============================================================
// fp16 flash attention: fp16 QKV in, cp.async double-buffered KV,
// ex2-based softmax (Q pre-scaled by 0.125*log2e). LPT qb order.
// ============================================================
#define AST 72
#define QS_OFF 0
#define KS_OFF (128 * AST)
#define VS_OFF (KS_OFF + 2 * 64 * AST)
#define FLASH_SMEM ((128 * AST + 4 * 64 * AST) * 2)   // 55296 bytes

__global__ __launch_bounds__(256) void flash_attn_mma(
    const __half* __restrict__ QKV, __half* __restrict__ Og)
{
    extern __shared__ __half sm[];

    int qb = (gridDim.x - 1) - blockIdx.x;   // LPT: biggest first
    int h = blockIdx.y, b = blockIdx.z;
    int q0 = qb * 128;
    int kvh = h >> 2;
    int tid = threadIdx.x, wid = tid >> 5, lane = tid & 31;
    int gr = lane >> 2, gc = lane & 3;
    int m0 = wid * 16;
    const int aro = ((lane & 8) ? 8 : 0) + (lane & 7);
    const int aco = (lane & 16) ? 8 : 0;
    const int bro = ((lane & 16) ? 8 : 0) + (lane & 7);
    const int bco = (lane & 8) ? 8 : 0;

    const uint32_t sm_u = (uint32_t)__cvta_generic_to_shared(sm);
    const uint32_t Qs_u = sm_u + QS_OFF * 2;

    const __half* Qbase = QKV + (size_t)(b * Tt + q0) * QKVN + h * HDim;
    const __half* KVbase = QKV + (size_t)(b * Tt) * QKVN + 1024 + kvh * HDim;

    // ---- stage Q via cp.async (fp16, pre-scaled) ----
#pragma unroll
    for (int i = 0; i < 4; i++) {
        int fi = i * 256 + tid;
        int row = fi >> 3, c8 = (fi & 7) * 8;
        cpa16(&sm[QS_OFF + row * AST + c8], Qbase + (size_t)row * QKVN + c8);
    }
    CP_COMMIT();

    auto issueKV = [&](int sbuf, int kt) {
        const __half* Kb = KVbase + (size_t)(kt * 64) * QKVN;
#pragma unroll
        for (int i = 0; i < 2; i++) {
            int fi = i * 256 + tid;
            int row = fi >> 3, c8 = (fi & 7) * 8;
            const __half* g = Kb + (size_t)row * QKVN + c8;
            cpa16(&sm[KS_OFF + sbuf * 64 * AST + row * AST + c8], g);
            cpa16(&sm[VS_OFF + sbuf * 64 * AST + row * AST + c8], g + 256);
        }
        CP_COMMIT();
    };

    issueKV(0, 0);
    CP_WAIT(1);         // Q done, KV0 may be in flight
    __syncthreads();

    uint32_t qf[4][4];
#pragma unroll
    for (int ks = 0; ks < 4; ks++)
        ldmx4(qf[ks], Qs_u + 2 * ((m0 + aro) * AST + ks * 16 + aco));

    float o[8][4];
#pragma unroll
    for (int nt = 0; nt < 8; nt++)
#pragma unroll
        for (int i = 0; i < 4; i++) o[nt][i] = 0.f;
    float m_lo = -1e30f, m_hi = -1e30f, l_lo = 0.f, l_hi = 0.f;

    const int row_lo = q0 + m0 + gr;
    const int row_hi = row_lo + 8;
    const int nkt = 2 * qb + 2;

    for (int kt = 0; kt < nkt; kt++) {
        int kv0 = kt * 64;
        int buf = kt & 1;
        CP_WAIT(0);          // this kt's KV resident
        __syncthreads();     // everyone done with buf^1 reads + KV visible
        if (kt + 1 < nkt) issueKV(buf ^ 1, kt + 1);

        uint32_t Ks_u = sm_u + (KS_OFF + buf * 64 * AST) * 2;
        uint32_t Vs_u = sm_u + (VS_OFF + buf * 64 * AST) * 2;

        // ---- S = Q K^T (log2-domain, Q pre-scaled) ----
        float s[8][4];
#pragma unroll
        for (int nt = 0; nt < 8; nt++)
#pragma unroll
            for (int i = 0; i < 4; i++) s[nt][i] = 0.f;

#pragma unroll
        for (int ks = 0; ks < 4; ks++) {
            uint32_t kf[4][4];
#pragma unroll
            for (int p = 0; p < 4; p++)
                ldmx4(kf[p], Ks_u + 2 * ((p * 16 + bro) * AST + ks * 16 + bco));
#pragma unroll
            for (int nt = 0; nt < 8; nt++) {
                int p = nt >> 1, hh = nt & 1;
                mma16816(s[nt], qf[ks][0], qf[ks][1], qf[ks][2], qf[ks][3],
                         kf[p][2 * hh], kf[p][2 * hh + 1]);
            }
        }

        if (kv0 + 63 > q0) {
#pragma unroll
            for (int nt = 0; nt < 8; nt++) {
                int c0 = kv0 + nt * 8 + 2 * gc;
                if (c0 > row_lo)     s[nt][0] = -1e30f;
                if (c0 + 1 > row_lo) s[nt][1] = -1e30f;
                if (c0 > row_hi)     s[nt][2] = -1e30f;
                if (c0 + 1 > row_hi) s[nt][3] = -1e30f;
            }
        }

        float tlo = -1e30f, thi = -1e30f;
#pragma unroll
        for (int nt = 0; nt < 8; nt++) {
            tlo = fmaxf(tlo, fmaxf(s[nt][0], s[nt][1]));
            thi = fmaxf(thi, fmaxf(s[nt][2], s[nt][3]));
        }
        tlo = fmaxf(tlo, __shfl_xor_sync(0xffffffffu, tlo, 1));
        tlo = fmaxf(tlo, __shfl_xor_sync(0xffffffffu, tlo, 2));
        thi = fmaxf(thi, __shfl_xor_sync(0xffffffffu, thi, 1));
        thi = fmaxf(thi, __shfl_xor_sync(0xffffffffu, thi, 2));

        float mn_lo = fmaxf(m_lo, tlo);
        float mn_hi = fmaxf(m_hi, thi);
        float cor_lo = ex2f(m_lo - mn_lo);
        float cor_hi = ex2f(m_hi - mn_hi);
        m_lo = mn_lo; m_hi = mn_hi;
        l_lo *= cor_lo; l_hi *= cor_hi;
#pragma unroll
        for (int nt = 0; nt < 8; nt++) {
            o[nt][0] *= cor_lo; o[nt][1] *= cor_lo;
            o[nt][2] *= cor_hi; o[nt][3] *= cor_hi;
        }

        // ---- P = 2^(S - m) -> smem (fp16, reuse Q buffer) ----
#pragma unroll
        for (int nt = 0; nt < 8; nt++) {
            float p0 = ex2f(s[nt][0] - m_lo);
            float p1 = ex2f(s[nt][1] - m_lo);
            float p2 = ex2f(s[nt][2] - m_hi);
            float p3 = ex2f(s[nt][3] - m_hi);
            l_lo += p0 + p1;
            l_hi += p2 + p3;
            *(__half2*)&sm[QS_OFF + (m0 + gr) * AST + nt * 8 + 2 * gc] =
                __floats2half2_rn(p0, p1);
            *(__half2*)&sm[QS_OFF + (m0 + 8 + gr) * AST + nt * 8 + 2 * gc] =
                __floats2half2_rn(p2, p3);
        }
        __syncthreads();

        // ---- O += P V ----
#pragma unroll
        for (int ks = 0; ks < 4; ks++) {
            uint32_t pf[4], vf[4][4];
            ldmx4(pf, Qs_u + 2 * ((m0 + aro) * AST + ks * 16 + aco));
#pragma unroll
            for (int p = 0; p < 4; p++)
                ldmx4t(vf[p], Vs_u + 2 * ((ks * 16 + aro) * AST + p * 16 + aco));
#pragma unroll
            for (int nt = 0; nt < 8; nt++) {
                int p = nt >> 1, hh = nt & 1;
                mma16816(o[nt], pf[0], pf[1], pf[2], pf[3],
                         vf[p][2 * hh], vf[p][2 * hh + 1]);
            }
        }
    }

    l_lo += __shfl_xor_sync(0xffffffffu, l_lo, 1);
    l_lo += __shfl_xor_sync(0xffffffffu, l_lo, 2);
    l_hi += __shfl_xor_sync(0xffffffffu, l_hi, 1);
    l_hi += __shfl_xor_sync(0xffffffffu, l_hi, 2);
    float inv_lo = 1.f / l_lo;
    float inv_hi = 1.f / l_hi;

    __half* Obase = Og + ((size_t)(b * Tt) * Hh + h) * HDim;
#pragma unroll
    for (int nt = 0; nt < 8; nt++) {
        int col = nt * 8 + 2 * gc;
        *(__half2*)&Obase[(size_t)row_lo * (Hh * HDim) + col] =
            __floats2half2_rn(o[nt][0] * inv_lo, o[nt][1] * inv_lo);
        *(__half2*)&Obase[(size_t)row_hi * (Hh * HDim) + col] =
            __floats2half2_rn(o[nt][2] * inv_hi, o[nt][3] * inv_hi);
    }
}

// ============================================================
// launch
// ============================================================
extern "C" void kernel_launch(void* const* d_in, const int* in_sizes, int n_in,
                              void* d_out, int out_size)
{
    const float* x  = (const float*)d_in[0];
    const float* cs = (const float*)d_in[1];
    const float* sn = (const float*)d_in[2];
    const float* Wq = (const float*)d_in[3];
    const float* Wk = (const float*)d_in[4];
    const float* Wv = (const float*)d_in[5];
    const float* Wo = (const float*)d_in[6];
    float* out = (float*)d_out;

    __half *Xh, *QKVh, *Yh, *WqkvTh, *WoTh;
    cudaGetSymbolAddress((void**)&Xh, g_Xh);
    cudaGetSymbolAddress((void**)&QKVh, g_QKVh);
    cudaGetSymbolAddress((void**)&Yh, g_Yh);
    cudaGetSymbolAddress((void**)&WqkvTh, g_WqkvTh);
    cudaGetSymbolAddress((void**)&WoTh, g_WoTh);

    cudaFuncSetAttribute(gemm_qkv,
                         cudaFuncAttributeMaxDynamicSharedMemorySize, QKV_SMEM);
    cudaFuncSetAttribute(gemm_mma,
                         cudaFuncAttributeMaxDynamicSharedMemorySize, GEMM_SMEM);
    cudaFuncSetAttribute(flash_attn_mma,
                         cudaFuncAttributeMaxDynamicSharedMemorySize, FLASH_SMEM);

    const int M = Bsz * Tt;  // 4096

    transpose_qkv<<<dim3(48, 32), dim3(32, 8)>>>(Wq, Wk, Wv, WqkvTh);
    transpose_k<<<dim3(32, 32), dim3(32, 8)>>>(Wo, WoTh, Cc, Cc);
    cvt_x<<<(M * Cc / 4) / 256, 256>>>(x, Xh);

    // fused QKV projection + rope + rms -> fp16 (Q pre-scaled)
    gemm_qkv<<<dim3(QKVN / 128, M / 128), 256, QKV_SMEM>>>(Xh, WqkvTh, QKVh, cs, sn);

    // causal GQA flash attention
    flash_attn_mma<<<dim3(Tt / 128, Hh, Bsz), 256, FLASH_SMEM>>>(QKVh, Yh);

    // output projection
    gemm_mma<<<dim3(Cc / 128, M / 128), 256, GEMM_SMEM>>>(Yh, WoTh, out, M, Cc, Cc);
}

// round 10
// speedup vs baseline: 2.2880x; 1.1097x over previous
#include <cuda_runtime.h>
#include <cuda_fp16.h>
#include <math.h>
#include <stdint.h>

#define Bsz 2
#define Tt  2048
#define Cc  1024
#define Hh  16
#define KVh 4
#define HDim 64
#define QKVN 1536   // 1024 Q + 256 K + 256 V
#define QSCALE 0.1803368801111204f   // 0.125 * log2(e)

// -------- scratch (static device globals; no allocation) --------
__device__ __align__(256) __half g_Xh[Bsz * Tt * Cc];
__device__ __align__(256) __half g_QKVh[Bsz * Tt * QKVN];   // fp16, Q pre-scaled
__device__ __align__(256) __half g_Yh[Bsz * Tt * Hh * HDim];
__device__ __align__(256) __half g_WqkvTh[QKVN * Cc];
__device__ __align__(256) __half g_WoTh[Cc * Cc];

__device__ __forceinline__ void mma16816(float* c,
    uint32_t a0, uint32_t a1, uint32_t a2, uint32_t a3,
    uint32_t b0, uint32_t b1) {
    asm volatile(
        "mma.sync.aligned.m16n8k16.row.col.f32.f16.f16.f32 "
        "{%0,%1,%2,%3}, {%4,%5,%6,%7}, {%8,%9}, {%0,%1,%2,%3};"
        : "+f"(c[0]), "+f"(c[1]), "+f"(c[2]), "+f"(c[3])
        : "r"(a0), "r"(a1), "r"(a2), "r"(a3), "r"(b0), "r"(b1));
}

__device__ __forceinline__ void ldmx4(uint32_t* r, uint32_t saddr) {
    asm volatile("ldmatrix.sync.aligned.m8n8.x4.shared.b16 {%0,%1,%2,%3}, [%4];"
        : "=r"(r[0]), "=r"(r[1]), "=r"(r[2]), "=r"(r[3]) : "r"(saddr));
}
__device__ __forceinline__ void ldmx4t(uint32_t* r, uint32_t saddr) {
    asm volatile("ldmatrix.sync.aligned.m8n8.x4.trans.shared.b16 {%0,%1,%2,%3}, [%4];"
        : "=r"(r[0]), "=r"(r[1]), "=r"(r[2]), "=r"(r[3]) : "r"(saddr));
}

__device__ __forceinline__ void cpa16(void* s, const void* g) {
    uint32_t sa = (uint32_t)__cvta_generic_to_shared(s);
    asm volatile("cp.async.ca.shared.global [%0], [%1], 16;" :: "r"(sa), "l"(g));
}
#define CP_COMMIT() asm volatile("cp.async.commit_group;" ::: "memory")
#define CP_WAIT(n)  asm volatile("cp.async.wait_group %0;" :: "n"(n) : "memory")

__device__ __forceinline__ float ex2f(float x) {
    float y;
    asm("ex2.approx.ftz.f32 %0, %1;" : "=f"(y) : "f"(x));
    return y;
}

// ============================================================
// x -> fp16
// ============================================================
__global__ __launch_bounds__(256) void cvt_x(
    const float* __restrict__ in, __half* __restrict__ out)
{
    int i = blockIdx.x * blockDim.x + threadIdx.x;
    float4 v = *(const float4*)(in + (size_t)i * 4);
    __half2* o = (__half2*)(out + (size_t)i * 4);
    o[0] = __floats2half2_rn(v.x, v.y);
    o[1] = __floats2half2_rn(v.z, v.w);
}

// ============================================================
// Fused QKV weight transpose -> fp16
// ============================================================
__global__ __launch_bounds__(256) void transpose_qkv(
    const float* __restrict__ Wq, const float* __restrict__ Wk,
    const float* __restrict__ Wv, __half* __restrict__ out)
{
    __shared__ float tile[32][33];
    int nblk = blockIdx.x;
    int k0 = blockIdx.y * 32;
    int tx = threadIdx.x, ty = threadIdx.y;

    const float* src;
    int N, nloc;
    if (nblk < 32)      { src = Wq; N = 1024; nloc = nblk * 32; }
    else if (nblk < 40) { src = Wk; N = 256;  nloc = (nblk - 32) * 32; }
    else                { src = Wv; N = 256;  nloc = (nblk - 40) * 32; }

#pragma unroll
    for (int i = 0; i < 32; i += 8)
        tile[ty + i][tx] = src[(size_t)(k0 + ty + i) * N + nloc + tx];
    __syncthreads();
#pragma unroll
    for (int i = 0; i < 32; i += 8)
        out[(size_t)(nblk * 32 + ty + i) * Cc + k0 + tx] = __float2half(tile[tx][ty + i]);
}

__global__ __launch_bounds__(256) void transpose_k(
    const float* __restrict__ in, __half* __restrict__ out, int K, int N)
{
    __shared__ float tile[32][33];
    int k0 = blockIdx.y * 32, n0 = blockIdx.x * 32;
    int tx = threadIdx.x, ty = threadIdx.y;
#pragma unroll
    for (int i = 0; i < 32; i += 8)
        tile[ty + i][tx] = in[(size_t)(k0 + ty + i) * N + n0 + tx];
    __syncthreads();
#pragma unroll
    for (int i = 0; i < 32; i += 8)
        out[(size_t)(n0 + ty + i) * K + k0 + tx] = __float2half(tile[tx][ty + i]);
}

// ============================================================
// GEMM common: 128 threads, 4 warps of 64x64 (CTA 128x128).
// K = 1024 fixed. 3-stage cp.async, ldmatrix, SMH=40 pad.
// ============================================================
#define SMH 40
#define STG_A (128 * SMH)
#define STAGE_H (2 * 128 * SMH)
#define GEMM_SMEM (3 * STAGE_H * 2)   // 61440 bytes

// mainloop as macro so both kernels share it exactly
#define GEMM_MAINLOOP(Aptr, Bptr)                                              \
    float acc[4][8][4];                                                        \
    _Pragma("unroll") for (int mt = 0; mt < 4; mt++)                           \
    _Pragma("unroll") for (int nt = 0; nt < 8; nt++)                           \
    _Pragma("unroll") for (int i = 0; i < 4; i++) acc[mt][nt][i] = 0.f;        \
    auto issue = [&](int st, int kc) {                                         \
        __half* As = sh + st * STAGE_H;                                        \
        __half* Bs = As + STG_A;                                               \
        _Pragma("unroll") for (int i = 0; i < 4; i++) {                        \
            int row = i * 32 + crow;                                           \
            cpa16(&As[row * SMH + ccol], Aptr + (size_t)(bm + row) * 1024 + kc + ccol); \
            cpa16(&Bs[row * SMH + ccol], Bptr + (size_t)(bn + row) * 1024 + kc + ccol); \
        }                                                                      \
        CP_COMMIT();                                                           \
    };                                                                         \
    issue(0, 0);                                                               \
    issue(1, 32);                                                              \
    int s = 0;                                                                 \
    for (int c = 0; c < 32; c++) {                                             \
        if (c == 31) { CP_WAIT(0); } else { CP_WAIT(1); }                      \
        __syncthreads();                                                       \
        if (c + 2 < 32) {                                                      \
            int s2 = s + 2; if (s2 >= 3) s2 -= 3;                              \
            issue(s2, (c + 2) * 32);                                           \
        }                                                                      \
        uint32_t As_u = sh_u + s * STAGE_H * 2;                                \
        uint32_t Bs_u = As_u + STG_A * 2;                                      \
        _Pragma("unroll") for (int ks = 0; ks < 2; ks++) {                     \
            int k0 = ks * 16;                                                  \
            uint32_t am[4][4], bmx[4][4];                                      \
            _Pragma("unroll") for (int mt = 0; mt < 4; mt++)                   \
                ldmx4(am[mt], As_u + 2 * ((m0 + mt * 16 + aro) * SMH + k0 + aco)); \
            _Pragma("unroll") for (int p = 0; p < 4; p++)                      \
                ldmx4(bmx[p], Bs_u + 2 * ((n0 + p * 16 + bro) * SMH + k0 + bco)); \
            _Pragma("unroll") for (int mt = 0; mt < 4; mt++)                   \
            _Pragma("unroll") for (int p = 0; p < 4; p++) {                    \
                mma16816(acc[mt][2 * p],     am[mt][0], am[mt][1], am[mt][2], am[mt][3], \
                         bmx[p][0], bmx[p][1]);                                \
                mma16816(acc[mt][2 * p + 1], am[mt][0], am[mt][1], am[mt][2], am[mt][3], \
                         bmx[p][2], bmx[p][3]);                                \
            }                                                                  \
        }                                                                      \
        if (++s >= 3) s -= 3;                                                  \
    }

#define GEMM_PROLOG                                                            \
    extern __shared__ __half sh[];                                             \
    int tid = threadIdx.x, wid = tid >> 5, lane = tid & 31;                    \
    int gr = lane >> 2, gc = lane & 3;                                         \
    int bm = blockIdx.y * 128, bn = blockIdx.x * 128;                          \
    int m0 = (wid & 1) * 64, n0 = (wid >> 1) * 64;                             \
    const int aro = ((lane & 8) ? 8 : 0) + (lane & 7);                         \
    const int aco = (lane & 16) ? 8 : 0;                                       \
    const int bro = ((lane & 16) ? 8 : 0) + (lane & 7);                        \
    const int bco = (lane & 8) ? 8 : 0;                                        \
    const int crow = tid >> 2;                                                 \
    const int ccol = (tid & 3) * 8;                                            \
    const uint32_t sh_u = (uint32_t)__cvta_generic_to_shared(sh);

// ============================================================
// QKV GEMM + register-local rope/rms epilogue -> fp16 QKVh.
// grid (12, 32). N-tiles: 0-7 Q (scaled), 8-9 K, 10-11 V.
// ============================================================
__global__ __launch_bounds__(128) void gemm_qkv(
    const __half* __restrict__ A, const __half* __restrict__ BT,
    __half* __restrict__ Og,
    const float* __restrict__ cosp, const float* __restrict__ sinp)
{
    GEMM_PROLOG
    GEMM_MAINLOOP(A, BT)

    int ntile = blockIdx.x;
    int hb = bn + n0;   // head-aligned (64) column base

    if (ntile >= 10) {
        // ---- V: plain fp16 store ----
#pragma unroll
        for (int mt = 0; mt < 4; mt++)
#pragma unroll
            for (int nt = 0; nt < 8; nt++) {
                int row = bm + m0 + mt * 16 + gr;
                int col = hb + nt * 8 + 2 * gc;
                *(__half2*)&Og[(size_t)row * QKVN + col] =
                    __floats2half2_rn(acc[mt][nt][0], acc[mt][nt][1]);
                *(__half2*)&Og[(size_t)(row + 8) * QKVN + col] =
                    __floats2half2_rn(acc[mt][nt][2], acc[mt][nt][3]);
            }
        return;
    }

    // ---- Q/K: rope + rms, all register-local (quad reductions) ----
    float scl = (ntile < 8) ? QSCALE : 1.0f;
#pragma unroll
    for (int mt = 0; mt < 4; mt++) {
#pragma unroll
        for (int j = 0; j < 2; j++) {
            int row = bm + m0 + mt * 16 + gr + j * 8;
            int t = row & (Tt - 1);
            float o1a[4][2], o2a[4][2];
            float ss = 0.f;
#pragma unroll
            for (int nt = 0; nt < 4; nt++) {
                int d = nt * 8 + 2 * gc;
                float2 c2 = *(const float2*)&cosp[t * 32 + d];
                float2 s2 = *(const float2*)&sinp[t * 32 + d];
#pragma unroll
                for (int i = 0; i < 2; i++) {
                    float cv = i ? c2.y : c2.x;
                    float sv = i ? s2.y : s2.x;
                    float x1 = acc[mt][nt][j * 2 + i];
                    float x2 = acc[mt][nt + 4][j * 2 + i];
                    float o1 = x1 * cv + x2 * sv;
                    float o2 = -x1 * sv + x2 * cv;
                    o1a[nt][i] = o1;
                    o2a[nt][i] = o2;
                    ss += o1 * o1 + o2 * o2;
                }
            }
            ss += __shfl_xor_sync(0xffffffffu, ss, 1);
            ss += __shfl_xor_sync(0xffffffffu, ss, 2);
            float inv = rsqrtf(ss * (1.0f / HDim) + 1e-6f) * scl;

            __half* og = Og + (size_t)row * QKVN + hb;
#pragma unroll
            for (int nt = 0; nt < 4; nt++) {
                int d = nt * 8 + 2 * gc;
                *(__half2*)&og[d] =
                    __floats2half2_rn(o1a[nt][0] * inv, o1a[nt][1] * inv);
                *(__half2*)&og[d + 32] =
                    __floats2half2_rn(o2a[nt][0] * inv, o2a[nt][1] * inv);
            }
        }
    }
}

// ============================================================
// Wo GEMM: fp16 in, fp32 out. grid (8, 32).
// ============================================================
__global__ __launch_bounds__(128) void gemm_wo(
    const __half* __restrict__ A, const __half* __restrict__ BT,
    float* __restrict__ C)
{
    GEMM_PROLOG
    GEMM_MAINLOOP(A, BT)

#pragma unroll
    for (int mt = 0; mt < 4; mt++)
#pragma unroll
        for (int nt = 0; nt < 8; nt++) {
            int row = bm + m0 + mt * 16 + gr;
            int col = bn + n0 + nt * 8 + 2 * gc;
            *(float2*)&C[(size_t)row * Cc + col] =
                make_float2(acc[mt][nt][0], acc[mt][nt][1]);
            *(float2*)&C[(size_t)(row + 8) * Cc + col] =
                make_float2(acc[mt][nt][2], acc[mt][nt][3]);
        }
}

// ============================================================
// fp16 flash attention (unchanged from R9)
// ============================================================
#define AST 72
#define QS_OFF 0
#define KS_OFF (128 * AST)
#define VS_OFF (KS_OFF + 2 * 64 * AST)
#define FLASH_SMEM ((128 * AST + 4 * 64 * AST) * 2)   // 55296 bytes

__global__ __launch_bounds__(256) void flash_attn_mma(
    const __half* __restrict__ QKV, __half* __restrict__ Og)
{
    extern __shared__ __half sm[];

    int qb = (gridDim.x - 1) - blockIdx.x;   // LPT: biggest first
    int h = blockIdx.y, b = blockIdx.z;
    int q0 = qb * 128;
    int kvh = h >> 2;
    int tid = threadIdx.x, wid = tid >> 5, lane = tid & 31;
    int gr = lane >> 2, gc = lane & 3;
    int m0 = wid * 16;
    const int aro = ((lane & 8) ? 8 : 0) + (lane & 7);
    const int aco = (lane & 16) ? 8 : 0;
    const int bro = ((lane & 16) ? 8 : 0) + (lane & 7);
    const int bco = (lane & 8) ? 8 : 0;

    const uint32_t sm_u = (uint32_t)__cvta_generic_to_shared(sm);
    const uint32_t Qs_u = sm_u + QS_OFF * 2;

    const __half* Qbase = QKV + (size_t)(b * Tt + q0) * QKVN + h * HDim;
    const __half* KVbase = QKV + (size_t)(b * Tt) * QKVN + 1024 + kvh * HDim;

#pragma unroll
    for (int i = 0; i < 4; i++) {
        int fi = i * 256 + tid;
        int row = fi >> 3, c8 = (fi & 7) * 8;
        cpa16(&sm[QS_OFF + row * AST + c8], Qbase + (size_t)row * QKVN + c8);
    }
    CP_COMMIT();

    auto issueKV = [&](int sbuf, int kt) {
        const __half* Kb = KVbase + (size_t)(kt * 64) * QKVN;
#pragma unroll
        for (int i = 0; i < 2; i++) {
            int fi = i * 256 + tid;
            int row = fi >> 3, c8 = (fi & 7) * 8;
            const __half* g = Kb + (size_t)row * QKVN + c8;
            cpa16(&sm[KS_OFF + sbuf * 64 * AST + row * AST + c8], g);
            cpa16(&sm[VS_OFF + sbuf * 64 * AST + row * AST + c8], g + 256);
        }
        CP_COMMIT();
    };

    issueKV(0, 0);
    CP_WAIT(1);
    __syncthreads();

    uint32_t qf[4][4];
#pragma unroll
    for (int ks = 0; ks < 4; ks++)
        ldmx4(qf[ks], Qs_u + 2 * ((m0 + aro) * AST + ks * 16 + aco));

    float o[8][4];
#pragma unroll
    for (int nt = 0; nt < 8; nt++)
#pragma unroll
        for (int i = 0; i < 4; i++) o[nt][i] = 0.f;
    float m_lo = -1e30f, m_hi = -1e30f, l_lo = 0.f, l_hi = 0.f;

    const int row_lo = q0 + m0 + gr;
    const int row_hi = row_lo + 8;
    const int nkt = 2 * qb + 2;

    for (int kt = 0; kt < nkt; kt++) {
        int kv0 = kt * 64;
        int buf = kt & 1;
        CP_WAIT(0);
        __syncthreads();
        if (kt + 1 < nkt) issueKV(buf ^ 1, kt + 1);

        uint32_t Ks_u = sm_u + (KS_OFF + buf * 64 * AST) * 2;
        uint32_t Vs_u = sm_u + (VS_OFF + buf * 64 * AST) * 2;

        float s[8][4];
#pragma unroll
        for (int nt = 0; nt < 8; nt++)
#pragma unroll
            for (int i = 0; i < 4; i++) s[nt][i] = 0.f;

#pragma unroll
        for (int ks = 0; ks < 4; ks++) {
            uint32_t kf[4][4];
#pragma unroll
            for (int p = 0; p < 4; p++)
                ldmx4(kf[p], Ks_u + 2 * ((p * 16 + bro) * AST + ks * 16 + bco));
#pragma unroll
            for (int nt = 0; nt < 8; nt++) {
                int p = nt >> 1, hh = nt & 1;
                mma16816(s[nt], qf[ks][0], qf[ks][1], qf[ks][2], qf[ks][3],
                         kf[p][2 * hh], kf[p][2 * hh + 1]);
            }
        }

        if (kv0 + 63 > q0) {
#pragma unroll
            for (int nt = 0; nt < 8; nt++) {
                int c0 = kv0 + nt * 8 + 2 * gc;
                if (c0 > row_lo)     s[nt][0] = -1e30f;
                if (c0 + 1 > row_lo) s[nt][1] = -1e30f;
                if (c0 > row_hi)     s[nt][2] = -1e30f;
                if (c0 + 1 > row_hi) s[nt][3] = -1e30f;
            }
        }

        float tlo = -1e30f, thi = -1e30f;
#pragma unroll
        for (int nt = 0; nt < 8; nt++) {
            tlo = fmaxf(tlo, fmaxf(s[nt][0], s[nt][1]));
            thi = fmaxf(thi, fmaxf(s[nt][2], s[nt][3]));
        }
        tlo = fmaxf(tlo, __shfl_xor_sync(0xffffffffu, tlo, 1));
        tlo = fmaxf(tlo, __shfl_xor_sync(0xffffffffu, tlo, 2));
        thi = fmaxf(thi, __shfl_xor_sync(0xffffffffu, thi, 1));
        thi = fmaxf(thi, __shfl_xor_sync(0xffffffffu, thi, 2));

        float mn_lo = fmaxf(m_lo, tlo);
        float mn_hi = fmaxf(m_hi, thi);
        float cor_lo = ex2f(m_lo - mn_lo);
        float cor_hi = ex2f(m_hi - mn_hi);
        m_lo = mn_lo; m_hi = mn_hi;
        l_lo *= cor_lo; l_hi *= cor_hi;
#pragma unroll
        for (int nt = 0; nt < 8; nt++) {
            o[nt][0] *= cor_lo; o[nt][1] *= cor_lo;
            o[nt][2] *= cor_hi; o[nt][3] *= cor_hi;
        }

#pragma unroll
        for (int nt = 0; nt < 8; nt++) {
            float p0 = ex2f(s[nt][0] - m_lo);
            float p1 = ex2f(s[nt][1] - m_lo);
            float p2 = ex2f(s[nt][2] - m_hi);
            float p3 = ex2f(s[nt][3] - m_hi);
            l_lo += p0 + p1;
            l_hi += p2 + p3;
            *(__half2*)&sm[QS_OFF + (m0 + gr) * AST + nt * 8 + 2 * gc] =
                __floats2half2_rn(p0, p1);
            *(__half2*)&sm[QS_OFF + (m0 + 8 + gr) * AST + nt * 8 + 2 * gc] =
                __floats2half2_rn(p2, p3);
        }
        __syncthreads();

#pragma unroll
        for (int ks = 0; ks < 4; ks++) {
            uint32_t pf[4], vf[4][4];
            ldmx4(pf, Qs_u + 2 * ((m0 + aro) * AST + ks * 16 + aco));
#pragma unroll
            for (int p = 0; p < 4; p++)
                ldmx4t(vf[p], Vs_u + 2 * ((ks * 16 + aro) * AST + p * 16 + aco));
#pragma unroll
            for (int nt = 0; nt < 8; nt++) {
                int p = nt >> 1, hh = nt & 1;
                mma16816(o[nt], pf[0], pf[1], pf[2], pf[3],
                         vf[p][2 * hh], vf[p][2 * hh + 1]);
            }
        }
    }

    l_lo += __shfl_xor_sync(0xffffffffu, l_lo, 1);
    l_lo += __shfl_xor_sync(0xffffffffu, l_lo, 2);
    l_hi += __shfl_xor_sync(0xffffffffu, l_hi, 1);
    l_hi += __shfl_xor_sync(0xffffffffu, l_hi, 2);
    float inv_lo = 1.f / l_lo;
    float inv_hi = 1.f / l_hi;

    __half* Obase = Og + ((size_t)(b * Tt) * Hh + h) * HDim;
#pragma unroll
    for (int nt = 0; nt < 8; nt++) {
        int col = nt * 8 + 2 * gc;
        *(__half2*)&Obase[(size_t)row_lo * (Hh * HDim) + col] =
            __floats2half2_rn(o[nt][0] * inv_lo, o[nt][1] * inv_lo);
        *(__half2*)&Obase[(size_t)row_hi * (Hh * HDim) + col] =
            __floats2half2_rn(o[nt][2] * inv_hi, o[nt][3] * inv_hi);
    }
}

// ============================================================
// launch
// ============================================================
extern "C" void kernel_launch(void* const* d_in, const int* in_sizes, int n_in,
                              void* d_out, int out_size)
{
    const float* x  = (const float*)d_in[0];
    const float* cs = (const float*)d_in[1];
    const float* sn = (const float*)d_in[2];
    const float* Wq = (const float*)d_in[3];
    const float* Wk = (const float*)d_in[4];
    const float* Wv = (const float*)d_in[5];
    const float* Wo = (const float*)d_in[6];
    float* out = (float*)d_out;

    __half *Xh, *QKVh, *Yh, *WqkvTh, *WoTh;
    cudaGetSymbolAddress((void**)&Xh, g_Xh);
    cudaGetSymbolAddress((void**)&QKVh, g_QKVh);
    cudaGetSymbolAddress((void**)&Yh, g_Yh);
    cudaGetSymbolAddress((void**)&WqkvTh, g_WqkvTh);
    cudaGetSymbolAddress((void**)&WoTh, g_WoTh);

    cudaFuncSetAttribute(gemm_qkv,
                         cudaFuncAttributeMaxDynamicSharedMemorySize, GEMM_SMEM);
    cudaFuncSetAttribute(gemm_wo,
                         cudaFuncAttributeMaxDynamicSharedMemorySize, GEMM_SMEM);
    cudaFuncSetAttribute(flash_attn_mma,
                         cudaFuncAttributeMaxDynamicSharedMemorySize, FLASH_SMEM);

    const int M = Bsz * Tt;  // 4096

    transpose_qkv<<<dim3(48, 32), dim3(32, 8)>>>(Wq, Wk, Wv, WqkvTh);
    transpose_k<<<dim3(32, 32), dim3(32, 8)>>>(Wo, WoTh, Cc, Cc);
    cvt_x<<<(M * Cc / 4) / 256, 256>>>(x, Xh);

    // fused QKV projection + rope + rms -> fp16 (Q pre-scaled)
    gemm_qkv<<<dim3(QKVN / 128, M / 128), 128, GEMM_SMEM>>>(Xh, WqkvTh, QKVh, cs, sn);

    // causal GQA flash attention
    flash_attn_mma<<<dim3(Tt / 128, Hh, Bsz), 256, FLASH_SMEM>>>(QKVh, Yh);

    // output projection
    gemm_wo<<<dim3(Cc / 128, M / 128), 128, GEMM_SMEM>>>(Yh, WoTh, out);
}

// round 11
// speedup vs baseline: 2.6035x; 1.1379x over previous
#include <cuda_runtime.h>
#include <cuda_fp16.h>
#include <math.h>
#include <stdint.h>

#define Bsz 2
#define Tt  2048
#define Cc  1024
#define Hh  16
#define KVh 4
#define HDim 64
#define QKVN 1536   // 1024 Q + 256 K + 256 V
#define QSCALE 0.1803368801111204f   // 0.125 * log2(e)

// -------- scratch (static device globals; no allocation) --------
__device__ __align__(256) __half g_Xh[Bsz * Tt * Cc];
__device__ __align__(256) __half g_QKVh[Bsz * Tt * QKVN];   // fp16, Q pre-scaled
__device__ __align__(256) __half g_Yh[Bsz * Tt * Hh * HDim];
__device__ __align__(256) __half g_WqkvTh[QKVN * Cc];
__device__ __align__(256) __half g_WoTh[Cc * Cc];

__device__ __forceinline__ void mma16816(float* c,
    uint32_t a0, uint32_t a1, uint32_t a2, uint32_t a3,
    uint32_t b0, uint32_t b1) {
    asm volatile(
        "mma.sync.aligned.m16n8k16.row.col.f32.f16.f16.f32 "
        "{%0,%1,%2,%3}, {%4,%5,%6,%7}, {%8,%9}, {%0,%1,%2,%3};"
        : "+f"(c[0]), "+f"(c[1]), "+f"(c[2]), "+f"(c[3])
        : "r"(a0), "r"(a1), "r"(a2), "r"(a3), "r"(b0), "r"(b1));
}

__device__ __forceinline__ void ldmx4(uint32_t* r, uint32_t saddr) {
    asm volatile("ldmatrix.sync.aligned.m8n8.x4.shared.b16 {%0,%1,%2,%3}, [%4];"
        : "=r"(r[0]), "=r"(r[1]), "=r"(r[2]), "=r"(r[3]) : "r"(saddr));
}
__device__ __forceinline__ void ldmx4t(uint32_t* r, uint32_t saddr) {
    asm volatile("ldmatrix.sync.aligned.m8n8.x4.trans.shared.b16 {%0,%1,%2,%3}, [%4];"
        : "=r"(r[0]), "=r"(r[1]), "=r"(r[2]), "=r"(r[3]) : "r"(saddr));
}

__device__ __forceinline__ void cpa16(void* s, const void* g) {
    uint32_t sa = (uint32_t)__cvta_generic_to_shared(s);
    asm volatile("cp.async.ca.shared.global [%0], [%1], 16;" :: "r"(sa), "l"(g));
}
#define CP_COMMIT() asm volatile("cp.async.commit_group;" ::: "memory")
#define CP_WAIT(n)  asm volatile("cp.async.wait_group %0;" :: "n"(n) : "memory")

__device__ __forceinline__ float ex2f(float x) {
    float y;
    asm("ex2.approx.ftz.f32 %0, %1;" : "=f"(y) : "f"(x));
    return y;
}
__device__ __forceinline__ uint32_t packh2(float a, float b) {
    __half2 h = __floats2half2_rn(a, b);
    return *reinterpret_cast<uint32_t*>(&h);
}

// ============================================================
// x -> fp16
// ============================================================
__global__ __launch_bounds__(256) void cvt_x(
    const float* __restrict__ in, __half* __restrict__ out)
{
    int i = blockIdx.x * blockDim.x + threadIdx.x;
    float4 v = *(const float4*)(in + (size_t)i * 4);
    __half2* o = (__half2*)(out + (size_t)i * 4);
    o[0] = __floats2half2_rn(v.x, v.y);
    o[1] = __floats2half2_rn(v.z, v.w);
}

// ============================================================
// Fused QKV weight transpose -> fp16
// ============================================================
__global__ __launch_bounds__(256) void transpose_qkv(
    const float* __restrict__ Wq, const float* __restrict__ Wk,
    const float* __restrict__ Wv, __half* __restrict__ out)
{
    __shared__ float tile[32][33];
    int nblk = blockIdx.x;
    int k0 = blockIdx.y * 32;
    int tx = threadIdx.x, ty = threadIdx.y;

    const float* src;
    int N, nloc;
    if (nblk < 32)      { src = Wq; N = 1024; nloc = nblk * 32; }
    else if (nblk < 40) { src = Wk; N = 256;  nloc = (nblk - 32) * 32; }
    else                { src = Wv; N = 256;  nloc = (nblk - 40) * 32; }

#pragma unroll
    for (int i = 0; i < 32; i += 8)
        tile[ty + i][tx] = src[(size_t)(k0 + ty + i) * N + nloc + tx];
    __syncthreads();
#pragma unroll
    for (int i = 0; i < 32; i += 8)
        out[(size_t)(nblk * 32 + ty + i) * Cc + k0 + tx] = __float2half(tile[tx][ty + i]);
}

__global__ __launch_bounds__(256) void transpose_k(
    const float* __restrict__ in, __half* __restrict__ out, int K, int N)
{
    __shared__ float tile[32][33];
    int k0 = blockIdx.y * 32, n0 = blockIdx.x * 32;
    int tx = threadIdx.x, ty = threadIdx.y;
#pragma unroll
    for (int i = 0; i < 32; i += 8)
        tile[ty + i][tx] = in[(size_t)(k0 + ty + i) * N + n0 + tx];
    __syncthreads();
#pragma unroll
    for (int i = 0; i < 32; i += 8)
        out[(size_t)(n0 + ty + i) * K + k0 + tx] = __float2half(tile[tx][ty + i]);
}

// ============================================================
// GEMM common: 128 threads, 4 warps of 64x64 (CTA 128x128).
// ============================================================
#define SMH 40
#define STG_A (128 * SMH)
#define STAGE_H (2 * 128 * SMH)
#define GEMM_SMEM (3 * STAGE_H * 2)   // 61440 bytes

#define GEMM_MAINLOOP(Aptr, Bptr)                                              \
    float acc[4][8][4];                                                        \
    _Pragma("unroll") for (int mt = 0; mt < 4; mt++)                           \
    _Pragma("unroll") for (int nt = 0; nt < 8; nt++)                           \
    _Pragma("unroll") for (int i = 0; i < 4; i++) acc[mt][nt][i] = 0.f;        \
    auto issue = [&](int st, int kc) {                                         \
        __half* As = sh + st * STAGE_H;                                        \
        __half* Bs = As + STG_A;                                               \
        _Pragma("unroll") for (int i = 0; i < 4; i++) {                        \
            int row = i * 32 + crow;                                           \
            cpa16(&As[row * SMH + ccol], Aptr + (size_t)(bm + row) * 1024 + kc + ccol); \
            cpa16(&Bs[row * SMH + ccol], Bptr + (size_t)(bn + row) * 1024 + kc + ccol); \
        }                                                                      \
        CP_COMMIT();                                                           \
    };                                                                         \
    issue(0, 0);                                                               \
    issue(1, 32);                                                              \
    int s = 0;                                                                 \
    for (int c = 0; c < 32; c++) {                                             \
        if (c == 31) { CP_WAIT(0); } else { CP_WAIT(1); }                      \
        __syncthreads();                                                       \
        if (c + 2 < 32) {                                                      \
            int s2 = s + 2; if (s2 >= 3) s2 -= 3;                              \
            issue(s2, (c + 2) * 32);                                           \
        }                                                                      \
        uint32_t As_u = sh_u + s * STAGE_H * 2;                                \
        uint32_t Bs_u = As_u + STG_A * 2;                                      \
        _Pragma("unroll") for (int ks = 0; ks < 2; ks++) {                     \
            int k0 = ks * 16;                                                  \
            uint32_t am[4][4], bmx[4][4];                                      \
            _Pragma("unroll") for (int mt = 0; mt < 4; mt++)                   \
                ldmx4(am[mt], As_u + 2 * ((m0 + mt * 16 + aro) * SMH + k0 + aco)); \
            _Pragma("unroll") for (int p = 0; p < 4; p++)                      \
                ldmx4(bmx[p], Bs_u + 2 * ((n0 + p * 16 + bro) * SMH + k0 + bco)); \
            _Pragma("unroll") for (int mt = 0; mt < 4; mt++)                   \
            _Pragma("unroll") for (int p = 0; p < 4; p++) {                    \
                mma16816(acc[mt][2 * p],     am[mt][0], am[mt][1], am[mt][2], am[mt][3], \
                         bmx[p][0], bmx[p][1]);                                \
                mma16816(acc[mt][2 * p + 1], am[mt][0], am[mt][1], am[mt][2], am[mt][3], \
                         bmx[p][2], bmx[p][3]);                                \
            }                                                                  \
        }                                                                      \
        if (++s >= 3) s -= 3;                                                  \
    }

#define GEMM_PROLOG                                                            \
    extern __shared__ __half sh[];                                             \
    int tid = threadIdx.x, wid = tid >> 5, lane = tid & 31;                    \
    int gr = lane >> 2, gc = lane & 3;                                         \
    int bm = blockIdx.y * 128, bn = blockIdx.x * 128;                          \
    int m0 = (wid & 1) * 64, n0 = (wid >> 1) * 64;                             \
    const int aro = ((lane & 8) ? 8 : 0) + (lane & 7);                         \
    const int aco = (lane & 16) ? 8 : 0;                                       \
    const int bro = ((lane & 16) ? 8 : 0) + (lane & 7);                        \
    const int bco = (lane & 8) ? 8 : 0;                                        \
    const int crow = tid >> 2;                                                 \
    const int ccol = (tid & 3) * 8;                                            \
    const uint32_t sh_u = (uint32_t)__cvta_generic_to_shared(sh);

// ============================================================
// QKV GEMM + register-local rope/rms epilogue -> fp16 QKVh.
// ============================================================
__global__ __launch_bounds__(128) void gemm_qkv(
    const __half* __restrict__ A, const __half* __restrict__ BT,
    __half* __restrict__ Og,
    const float* __restrict__ cosp, const float* __restrict__ sinp)
{
    GEMM_PROLOG
    GEMM_MAINLOOP(A, BT)

    int ntile = blockIdx.x;
    int hb = bn + n0;

    if (ntile >= 10) {
#pragma unroll
        for (int mt = 0; mt < 4; mt++)
#pragma unroll
            for (int nt = 0; nt < 8; nt++) {
                int row = bm + m0 + mt * 16 + gr;
                int col = hb + nt * 8 + 2 * gc;
                *(__half2*)&Og[(size_t)row * QKVN + col] =
                    __floats2half2_rn(acc[mt][nt][0], acc[mt][nt][1]);
                *(__half2*)&Og[(size_t)(row + 8) * QKVN + col] =
                    __floats2half2_rn(acc[mt][nt][2], acc[mt][nt][3]);
            }
        return;
    }

    float scl = (ntile < 8) ? QSCALE : 1.0f;
#pragma unroll
    for (int mt = 0; mt < 4; mt++) {
#pragma unroll
        for (int j = 0; j < 2; j++) {
            int row = bm + m0 + mt * 16 + gr + j * 8;
            int t = row & (Tt - 1);
            float o1a[4][2], o2a[4][2];
            float ss = 0.f;
#pragma unroll
            for (int nt = 0; nt < 4; nt++) {
                int d = nt * 8 + 2 * gc;
                float2 c2 = *(const float2*)&cosp[t * 32 + d];
                float2 s2 = *(const float2*)&sinp[t * 32 + d];
#pragma unroll
                for (int i = 0; i < 2; i++) {
                    float cv = i ? c2.y : c2.x;
                    float sv = i ? s2.y : s2.x;
                    float x1 = acc[mt][nt][j * 2 + i];
                    float x2 = acc[mt][nt + 4][j * 2 + i];
                    float o1 = x1 * cv + x2 * sv;
                    float o2 = -x1 * sv + x2 * cv;
                    o1a[nt][i] = o1;
                    o2a[nt][i] = o2;
                    ss += o1 * o1 + o2 * o2;
                }
            }
            ss += __shfl_xor_sync(0xffffffffu, ss, 1);
            ss += __shfl_xor_sync(0xffffffffu, ss, 2);
            float inv = rsqrtf(ss * (1.0f / HDim) + 1e-6f) * scl;

            __half* og = Og + (size_t)row * QKVN + hb;
#pragma unroll
            for (int nt = 0; nt < 4; nt++) {
                int d = nt * 8 + 2 * gc;
                *(__half2*)&og[d] =
                    __floats2half2_rn(o1a[nt][0] * inv, o1a[nt][1] * inv);
                *(__half2*)&og[d + 32] =
                    __floats2half2_rn(o2a[nt][0] * inv, o2a[nt][1] * inv);
            }
        }
    }
}

// ============================================================
// Wo GEMM: fp16 in, fp32 out.
// ============================================================
__global__ __launch_bounds__(128) void gemm_wo(
    const __half* __restrict__ A, const __half* __restrict__ BT,
    float* __restrict__ C)
{
    GEMM_PROLOG
    GEMM_MAINLOOP(A, BT)

#pragma unroll
    for (int mt = 0; mt < 4; mt++)
#pragma unroll
        for (int nt = 0; nt < 8; nt++) {
            int row = bm + m0 + mt * 16 + gr;
            int col = bn + n0 + nt * 8 + 2 * gc;
            *(float2*)&C[(size_t)row * Cc + col] =
                make_float2(acc[mt][nt][0], acc[mt][nt][1]);
            *(float2*)&C[(size_t)(row + 8) * Cc + col] =
                make_float2(acc[mt][nt][2], acc[mt][nt][3]);
        }
}

// ============================================================
// fp16 flash attention: 128 threads, 4 warps x 32 q-rows,
// register-resident P (no smem roundtrip), 1 barrier per tile.
// ============================================================
#define AST 72
#define QS_OFF 0
#define KS_OFF (128 * AST)
#define VS_OFF (KS_OFF + 2 * 64 * AST)
#define FLASH_SMEM ((128 * AST + 4 * 64 * AST) * 2)   // 55296 bytes

__global__ __launch_bounds__(128) void flash_attn_mma(
    const __half* __restrict__ QKV, __half* __restrict__ Og)
{
    extern __shared__ __half sm[];

    int qb = (gridDim.x - 1) - blockIdx.x;   // LPT: biggest first
    int h = blockIdx.y, b = blockIdx.z;
    int q0 = qb * 128;
    int kvh = h >> 2;
    int tid = threadIdx.x, wid = tid >> 5, lane = tid & 31;
    int gr = lane >> 2, gc = lane & 3;
    int m0 = wid * 32;
    const int aro = ((lane & 8) ? 8 : 0) + (lane & 7);
    const int aco = (lane & 16) ? 8 : 0;
    const int bro = ((lane & 16) ? 8 : 0) + (lane & 7);
    const int bco = (lane & 8) ? 8 : 0;

    const uint32_t sm_u = (uint32_t)__cvta_generic_to_shared(sm);
    const uint32_t Qs_u = sm_u + QS_OFF * 2;

    const __half* Qbase = QKV + (size_t)(b * Tt + q0) * QKVN + h * HDim;
    const __half* KVbase = QKV + (size_t)(b * Tt) * QKVN + 1024 + kvh * HDim;

    // ---- stage Q (fp16, pre-scaled by QSCALE) ----
#pragma unroll
    for (int i = 0; i < 8; i++) {
        int fi = i * 128 + tid;
        int row = fi >> 3, c8 = (fi & 7) * 8;
        cpa16(&sm[QS_OFF + row * AST + c8], Qbase + (size_t)row * QKVN + c8);
    }
    CP_COMMIT();

    auto issueKV = [&](int sbuf, int kt) {
        const __half* Kb = KVbase + (size_t)(kt * 64) * QKVN;
#pragma unroll
        for (int i = 0; i < 4; i++) {
            int fi = i * 128 + tid;
            int row = fi >> 3, c8 = (fi & 7) * 8;
            const __half* g = Kb + (size_t)row * QKVN + c8;
            cpa16(&sm[KS_OFF + sbuf * 64 * AST + row * AST + c8], g);
            cpa16(&sm[VS_OFF + sbuf * 64 * AST + row * AST + c8], g + 256);
        }
        CP_COMMIT();
    };

    issueKV(0, 0);
    CP_WAIT(1);
    __syncthreads();

    // ---- Q fragments: 2 m-tiles x 4 k-steps ----
    uint32_t qf[2][4][4];
#pragma unroll
    for (int mt = 0; mt < 2; mt++)
#pragma unroll
        for (int ks = 0; ks < 4; ks++)
            ldmx4(qf[mt][ks], Qs_u + 2 * ((m0 + mt * 16 + aro) * AST + ks * 16 + aco));

    float o[2][8][4];
#pragma unroll
    for (int mt = 0; mt < 2; mt++)
#pragma unroll
        for (int nt = 0; nt < 8; nt++)
#pragma unroll
            for (int i = 0; i < 4; i++) o[mt][nt][i] = 0.f;
    float mx[2][2], lsum[2][2];
#pragma unroll
    for (int mt = 0; mt < 2; mt++) {
        mx[mt][0] = -1e30f; mx[mt][1] = -1e30f;
        lsum[mt][0] = 0.f;  lsum[mt][1] = 0.f;
    }

    const int nkt = 2 * qb + 2;

    for (int kt = 0; kt < nkt; kt++) {
        int kv0 = kt * 64;
        int buf = kt & 1;
        CP_WAIT(0);
        __syncthreads();
        if (kt + 1 < nkt) issueKV(buf ^ 1, kt + 1);

        uint32_t Ks_u = sm_u + (KS_OFF + buf * 64 * AST) * 2;
        uint32_t Vs_u = sm_u + (VS_OFF + buf * 64 * AST) * 2;

        // ---- S = Q K^T ----
        float s[2][8][4];
#pragma unroll
        for (int mt = 0; mt < 2; mt++)
#pragma unroll
            for (int nt = 0; nt < 8; nt++)
#pragma unroll
                for (int i = 0; i < 4; i++) s[mt][nt][i] = 0.f;

#pragma unroll
        for (int ks = 0; ks < 4; ks++) {
            uint32_t kf[4][4];
#pragma unroll
            for (int p = 0; p < 4; p++)
                ldmx4(kf[p], Ks_u + 2 * ((p * 16 + bro) * AST + ks * 16 + bco));
#pragma unroll
            for (int mt = 0; mt < 2; mt++)
#pragma unroll
                for (int nt = 0; nt < 8; nt++) {
                    int p = nt >> 1, hh = nt & 1;
                    mma16816(s[mt][nt],
                             qf[mt][ks][0], qf[mt][ks][1], qf[mt][ks][2], qf[mt][ks][3],
                             kf[p][2 * hh], kf[p][2 * hh + 1]);
                }
        }

        // ---- causal mask (diagonal region only) ----
        if (kv0 + 63 > q0) {
#pragma unroll
            for (int mt = 0; mt < 2; mt++) {
                int rl = q0 + m0 + mt * 16 + gr;
                int rh = rl + 8;
#pragma unroll
                for (int nt = 0; nt < 8; nt++) {
                    int c0 = kv0 + nt * 8 + 2 * gc;
                    if (c0 > rl)     s[mt][nt][0] = -1e30f;
                    if (c0 + 1 > rl) s[mt][nt][1] = -1e30f;
                    if (c0 > rh)     s[mt][nt][2] = -1e30f;
                    if (c0 + 1 > rh) s[mt][nt][3] = -1e30f;
                }
            }
        }

        // ---- online softmax + register-resident P ----
        uint32_t pf[2][4][4];
#pragma unroll
        for (int mt = 0; mt < 2; mt++) {
            float tlo = -1e30f, thi = -1e30f;
#pragma unroll
            for (int nt = 0; nt < 8; nt++) {
                tlo = fmaxf(tlo, fmaxf(s[mt][nt][0], s[mt][nt][1]));
                thi = fmaxf(thi, fmaxf(s[mt][nt][2], s[mt][nt][3]));
            }
            tlo = fmaxf(tlo, __shfl_xor_sync(0xffffffffu, tlo, 1));
            tlo = fmaxf(tlo, __shfl_xor_sync(0xffffffffu, tlo, 2));
            thi = fmaxf(thi, __shfl_xor_sync(0xffffffffu, thi, 1));
            thi = fmaxf(thi, __shfl_xor_sync(0xffffffffu, thi, 2));

            float mn_lo = fmaxf(mx[mt][0], tlo);
            float mn_hi = fmaxf(mx[mt][1], thi);
            float cor_lo = ex2f(mx[mt][0] - mn_lo);
            float cor_hi = ex2f(mx[mt][1] - mn_hi);
            mx[mt][0] = mn_lo; mx[mt][1] = mn_hi;
            lsum[mt][0] *= cor_lo; lsum[mt][1] *= cor_hi;
#pragma unroll
            for (int nt = 0; nt < 8; nt++) {
                o[mt][nt][0] *= cor_lo; o[mt][nt][1] *= cor_lo;
                o[mt][nt][2] *= cor_hi; o[mt][nt][3] *= cor_hi;
            }

#pragma unroll
            for (int ks = 0; ks < 4; ks++) {
                float a0 = ex2f(s[mt][2 * ks][0] - mn_lo);
                float a1 = ex2f(s[mt][2 * ks][1] - mn_lo);
                float a2 = ex2f(s[mt][2 * ks][2] - mn_hi);
                float a3 = ex2f(s[mt][2 * ks][3] - mn_hi);
                float b0 = ex2f(s[mt][2 * ks + 1][0] - mn_lo);
                float b1 = ex2f(s[mt][2 * ks + 1][1] - mn_lo);
                float b2 = ex2f(s[mt][2 * ks + 1][2] - mn_hi);
                float b3 = ex2f(s[mt][2 * ks + 1][3] - mn_hi);
                lsum[mt][0] += a0 + a1 + b0 + b1;
                lsum[mt][1] += a2 + a3 + b2 + b3;
                pf[mt][ks][0] = packh2(a0, a1);
                pf[mt][ks][1] = packh2(a2, a3);
                pf[mt][ks][2] = packh2(b0, b1);
                pf[mt][ks][3] = packh2(b2, b3);
            }
        }

        // ---- O += P V ----
#pragma unroll
        for (int ks = 0; ks < 4; ks++) {
            uint32_t vf[4][4];
#pragma unroll
            for (int p = 0; p < 4; p++)
                ldmx4t(vf[p], Vs_u + 2 * ((ks * 16 + aro) * AST + p * 16 + aco));
#pragma unroll
            for (int mt = 0; mt < 2; mt++)
#pragma unroll
                for (int nt = 0; nt < 8; nt++) {
                    int p = nt >> 1, hh = nt & 1;
                    mma16816(o[mt][nt],
                             pf[mt][ks][0], pf[mt][ks][1], pf[mt][ks][2], pf[mt][ks][3],
                             vf[p][2 * hh], vf[p][2 * hh + 1]);
                }
        }
    }

    // ---- finalize ----
    __half* Obase = Og + ((size_t)(b * Tt) * Hh + h) * HDim;
#pragma unroll
    for (int mt = 0; mt < 2; mt++) {
        float llo = lsum[mt][0], lhi = lsum[mt][1];
        llo += __shfl_xor_sync(0xffffffffu, llo, 1);
        llo += __shfl_xor_sync(0xffffffffu, llo, 2);
        lhi += __shfl_xor_sync(0xffffffffu, lhi, 1);
        lhi += __shfl_xor_sync(0xffffffffu, lhi, 2);
        float inv_lo = 1.f / llo;
        float inv_hi = 1.f / lhi;

        int row_lo = q0 + m0 + mt * 16 + gr;
        int row_hi = row_lo + 8;
#pragma unroll
        for (int nt = 0; nt < 8; nt++) {
            int col = nt * 8 + 2 * gc;
            *(__half2*)&Obase[(size_t)row_lo * (Hh * HDim) + col] =
                __floats2half2_rn(o[mt][nt][0] * inv_lo, o[mt][nt][1] * inv_lo);
            *(__half2*)&Obase[(size_t)row_hi * (Hh * HDim) + col] =
                __floats2half2_rn(o[mt][nt][2] * inv_hi, o[mt][nt][3] * inv_hi);
        }
    }
}

// ============================================================
// launch
// ============================================================
extern "C" void kernel_launch(void* const* d_in, const int* in_sizes, int n_in,
                              void* d_out, int out_size)
{
    const float* x  = (const float*)d_in[0];
    const float* cs = (const float*)d_in[1];
    const float* sn = (const float*)d_in[2];
    const float* Wq = (const float*)d_in[3];
    const float* Wk = (const float*)d_in[4];
    const float* Wv = (const float*)d_in[5];
    const float* Wo = (const float*)d_in[6];
    float* out = (float*)d_out;

    __half *Xh, *QKVh, *Yh, *WqkvTh, *WoTh;
    cudaGetSymbolAddress((void**)&Xh, g_Xh);
    cudaGetSymbolAddress((void**)&QKVh, g_QKVh);
    cudaGetSymbolAddress((void**)&Yh, g_Yh);
    cudaGetSymbolAddress((void**)&WqkvTh, g_WqkvTh);
    cudaGetSymbolAddress((void**)&WoTh, g_WoTh);

    cudaFuncSetAttribute(gemm_qkv,
                         cudaFuncAttributeMaxDynamicSharedMemorySize, GEMM_SMEM);
    cudaFuncSetAttribute(gemm_wo,
                         cudaFuncAttributeMaxDynamicSharedMemorySize, GEMM_SMEM);
    cudaFuncSetAttribute(flash_attn_mma,
                         cudaFuncAttributeMaxDynamicSharedMemorySize, FLASH_SMEM);

    const int M = Bsz * Tt;  // 4096

    transpose_qkv<<<dim3(48, 32), dim3(32, 8)>>>(Wq, Wk, Wv, WqkvTh);
    transpose_k<<<dim3(32, 32), dim3(32, 8)>>>(Wo, WoTh, Cc, Cc);
    cvt_x<<<(M * Cc / 4) / 256, 256>>>(x, Xh);

    // fused QKV projection + rope + rms -> fp16 (Q pre-scaled)
    gemm_qkv<<<dim3(QKVN / 128, M / 128), 128, GEMM_SMEM>>>(Xh, WqkvTh, QKVh, cs, sn);

    // causal GQA flash attention (register-resident P)
    flash_attn_mma<<<dim3(Tt / 128, Hh, Bsz), 128, FLASH_SMEM>>>(QKVh, Yh);

    // output projection
    gemm_wo<<<dim3(Cc / 128, M / 128), 128, GEMM_SMEM>>>(Yh, WoTh, out);
}

// round 12
// speedup vs baseline: 2.6580x; 1.0209x over previous
#include <cuda_runtime.h>
#include <cuda_fp16.h>
#include <math.h>
#include <stdint.h>

#define Bsz 2
#define Tt  2048
#define Cc  1024
#define Hh  16
#define KVh 4
#define HDim 64
#define QKVN 1536   // 1024 Q + 256 K + 256 V
#define QSCALE 0.1803368801111204f   // 0.125 * log2(e)

// -------- scratch (static device globals; no allocation) --------
__device__ __align__(256) __half g_Xh[Bsz * Tt * Cc];
__device__ __align__(256) __half g_QKVh[Bsz * Tt * QKVN];   // fp16, Q pre-scaled
__device__ __align__(256) __half g_Yh[Bsz * Tt * Hh * HDim];
__device__ __align__(256) __half g_WqkvTh[QKVN * Cc];
__device__ __align__(256) __half g_WoTh[Cc * Cc];

__device__ __forceinline__ void mma16816(float* c,
    uint32_t a0, uint32_t a1, uint32_t a2, uint32_t a3,
    uint32_t b0, uint32_t b1) {
    asm volatile(
        "mma.sync.aligned.m16n8k16.row.col.f32.f16.f16.f32 "
        "{%0,%1,%2,%3}, {%4,%5,%6,%7}, {%8,%9}, {%0,%1,%2,%3};"
        : "+f"(c[0]), "+f"(c[1]), "+f"(c[2]), "+f"(c[3])
        : "r"(a0), "r"(a1), "r"(a2), "r"(a3), "r"(b0), "r"(b1));
}

__device__ __forceinline__ void ldmx4(uint32_t* r, uint32_t saddr) {
    asm volatile("ldmatrix.sync.aligned.m8n8.x4.shared.b16 {%0,%1,%2,%3}, [%4];"
        : "=r"(r[0]), "=r"(r[1]), "=r"(r[2]), "=r"(r[3]) : "r"(saddr));
}
__device__ __forceinline__ void ldmx4t(uint32_t* r, uint32_t saddr) {
    asm volatile("ldmatrix.sync.aligned.m8n8.x4.trans.shared.b16 {%0,%1,%2,%3}, [%4];"
        : "=r"(r[0]), "=r"(r[1]), "=r"(r[2]), "=r"(r[3]) : "r"(saddr));
}

__device__ __forceinline__ void cpa16(void* s, const void* g) {
    uint32_t sa = (uint32_t)__cvta_generic_to_shared(s);
    asm volatile("cp.async.ca.shared.global [%0], [%1], 16;" :: "r"(sa), "l"(g));
}
#define CP_COMMIT() asm volatile("cp.async.commit_group;" ::: "memory")
#define CP_WAIT(n)  asm volatile("cp.async.wait_group %0;" :: "n"(n) : "memory")

__device__ __forceinline__ float ex2f(float x) {
    float y;
    asm("ex2.approx.ftz.f32 %0, %1;" : "=f"(y) : "f"(x));
    return y;
}
__device__ __forceinline__ uint32_t packh2(float a, float b) {
    __half2 h = __floats2half2_rn(a, b);
    return *reinterpret_cast<uint32_t*>(&h);
}

// ============================================================
// Fused prep: cvt_x (blocks 0..4095), transpose_qkv
// (blocks 4096..5631), transpose Wo (blocks 5632..6655).
// ============================================================
#define PREP_CVT 4096
#define PREP_QKV 1536
#define PREP_WO  1024
#define PREP_GRID (PREP_CVT + PREP_QKV + PREP_WO)

__global__ __launch_bounds__(256) void prep(
    const float* __restrict__ x,
    const float* __restrict__ Wq, const float* __restrict__ Wk,
    const float* __restrict__ Wv, const float* __restrict__ Wo,
    __half* __restrict__ Xh, __half* __restrict__ WqkvTh,
    __half* __restrict__ WoTh)
{
    int blk = blockIdx.x;
    int tid = threadIdx.x;

    if (blk < PREP_CVT) {
        int i = blk * 256 + tid;
        float4 v = *(const float4*)(x + (size_t)i * 4);
        __half2* o = (__half2*)(Xh + (size_t)i * 4);
        o[0] = __floats2half2_rn(v.x, v.y);
        o[1] = __floats2half2_rn(v.z, v.w);
        return;
    }

    __shared__ float tile[32][33];
    int tx = tid & 31, ty = tid >> 5;   // 32 x 8
    const float* src;
    __half* dst;
    int N, nloc, k0, orow;

    if (blk < PREP_CVT + PREP_QKV) {
        int b = blk - PREP_CVT;
        int nblk = b % 48;
        k0 = (b / 48) * 32;
        if (nblk < 32)      { src = Wq; N = 1024; nloc = nblk * 32; }
        else if (nblk < 40) { src = Wk; N = 256;  nloc = (nblk - 32) * 32; }
        else                { src = Wv; N = 256;  nloc = (nblk - 40) * 32; }
        dst = WqkvTh; orow = nblk * 32;
    } else {
        int b = blk - PREP_CVT - PREP_QKV;
        src = Wo; N = 1024;
        nloc = (b % 32) * 32;
        k0 = (b / 32) * 32;
        dst = WoTh; orow = nloc;
    }

#pragma unroll
    for (int i = 0; i < 32; i += 8)
        tile[ty + i][tx] = src[(size_t)(k0 + ty + i) * N + nloc + tx];
    __syncthreads();
#pragma unroll
    for (int i = 0; i < 32; i += 8)
        dst[(size_t)(orow + ty + i) * Cc + k0 + tx] = __float2half(tile[tx][ty + i]);
}

// ============================================================
// GEMM common: 128 threads, 4 warps of 64x64 (CTA 128x128).
// ============================================================
#define SMH 40
#define STG_A (128 * SMH)
#define STAGE_H (2 * 128 * SMH)
#define GEMM_SMEM (3 * STAGE_H * 2)   // 61440 bytes

#define GEMM_MAINLOOP(Aptr, Bptr)                                              \
    float acc[4][8][4];                                                        \
    _Pragma("unroll") for (int mt = 0; mt < 4; mt++)                           \
    _Pragma("unroll") for (int nt = 0; nt < 8; nt++)                           \
    _Pragma("unroll") for (int i = 0; i < 4; i++) acc[mt][nt][i] = 0.f;        \
    auto issue = [&](int st, int kc) {                                         \
        __half* As = sh + st * STAGE_H;                                        \
        __half* Bs = As + STG_A;                                               \
        _Pragma("unroll") for (int i = 0; i < 4; i++) {                        \
            int row = i * 32 + crow;                                           \
            cpa16(&As[row * SMH + ccol], Aptr + (size_t)(bm + row) * 1024 + kc + ccol); \
            cpa16(&Bs[row * SMH + ccol], Bptr + (size_t)(bn + row) * 1024 + kc + ccol); \
        }                                                                      \
        CP_COMMIT();                                                           \
    };                                                                         \
    issue(0, 0);                                                               \
    issue(1, 32);                                                              \
    int s = 0;                                                                 \
    for (int c = 0; c < 32; c++) {                                             \
        if (c == 31) { CP_WAIT(0); } else { CP_WAIT(1); }                      \
        __syncthreads();                                                       \
        if (c + 2 < 32) {                                                      \
            int s2 = s + 2; if (s2 >= 3) s2 -= 3;                              \
            issue(s2, (c + 2) * 32);                                           \
        }                                                                      \
        uint32_t As_u = sh_u + s * STAGE_H * 2;                                \
        uint32_t Bs_u = As_u + STG_A * 2;                                      \
        _Pragma("unroll") for (int ks = 0; ks < 2; ks++) {                     \
            int k0 = ks * 16;                                                  \
            uint32_t am[4][4], bmx[4][4];                                      \
            _Pragma("unroll") for (int mt = 0; mt < 4; mt++)                   \
                ldmx4(am[mt], As_u + 2 * ((m0 + mt * 16 + aro) * SMH + k0 + aco)); \
            _Pragma("unroll") for (int p = 0; p < 4; p++)                      \
                ldmx4(bmx[p], Bs_u + 2 * ((n0 + p * 16 + bro) * SMH + k0 + bco)); \
            _Pragma("unroll") for (int mt = 0; mt < 4; mt++)                   \
            _Pragma("unroll") for (int p = 0; p < 4; p++) {                    \
                mma16816(acc[mt][2 * p],     am[mt][0], am[mt][1], am[mt][2], am[mt][3], \
                         bmx[p][0], bmx[p][1]);                                \
                mma16816(acc[mt][2 * p + 1], am[mt][0], am[mt][1], am[mt][2], am[mt][3], \
                         bmx[p][2], bmx[p][3]);                                \
            }                                                                  \
        }                                                                      \
        if (++s >= 3) s -= 3;                                                  \
    }

#define GEMM_PROLOG                                                            \
    extern __shared__ __half sh[];                                             \
    int tid = threadIdx.x, wid = tid >> 5, lane = tid & 31;                    \
    int gr = lane >> 2, gc = lane & 3;                                         \
    int bm = blockIdx.y * 128, bn = blockIdx.x * 128;                          \
    int m0 = (wid & 1) * 64, n0 = (wid >> 1) * 64;                             \
    const int aro = ((lane & 8) ? 8 : 0) + (lane & 7);                         \
    const int aco = (lane & 16) ? 8 : 0;                                       \
    const int bro = ((lane & 16) ? 8 : 0) + (lane & 7);                        \
    const int bco = (lane & 8) ? 8 : 0;                                        \
    const int crow = tid >> 2;                                                 \
    const int ccol = (tid & 3) * 8;                                            \
    const uint32_t sh_u = (uint32_t)__cvta_generic_to_shared(sh);

// ============================================================
// QKV GEMM + register-local rope/rms epilogue -> fp16 QKVh.
// ============================================================
__global__ __launch_bounds__(128, 3) void gemm_qkv(
    const __half* __restrict__ A, const __half* __restrict__ BT,
    __half* __restrict__ Og,
    const float* __restrict__ cosp, const float* __restrict__ sinp)
{
    GEMM_PROLOG
    GEMM_MAINLOOP(A, BT)

    int ntile = blockIdx.x;
    int hb = bn + n0;

    if (ntile >= 10) {
#pragma unroll
        for (int mt = 0; mt < 4; mt++)
#pragma unroll
            for (int nt = 0; nt < 8; nt++) {
                int row = bm + m0 + mt * 16 + gr;
                int col = hb + nt * 8 + 2 * gc;
                *(__half2*)&Og[(size_t)row * QKVN + col] =
                    __floats2half2_rn(acc[mt][nt][0], acc[mt][nt][1]);
                *(__half2*)&Og[(size_t)(row + 8) * QKVN + col] =
                    __floats2half2_rn(acc[mt][nt][2], acc[mt][nt][3]);
            }
        return;
    }

    float scl = (ntile < 8) ? QSCALE : 1.0f;
#pragma unroll
    for (int mt = 0; mt < 4; mt++) {
#pragma unroll
        for (int j = 0; j < 2; j++) {
            int row = bm + m0 + mt * 16 + gr + j * 8;
            int t = row & (Tt - 1);
            float o1a[4][2], o2a[4][2];
            float ss = 0.f;
#pragma unroll
            for (int nt = 0; nt < 4; nt++) {
                int d = nt * 8 + 2 * gc;
                float2 c2 = *(const float2*)&cosp[t * 32 + d];
                float2 s2 = *(const float2*)&sinp[t * 32 + d];
#pragma unroll
                for (int i = 0; i < 2; i++) {
                    float cv = i ? c2.y : c2.x;
                    float sv = i ? s2.y : s2.x;
                    float x1 = acc[mt][nt][j * 2 + i];
                    float x2 = acc[mt][nt + 4][j * 2 + i];
                    float o1 = x1 * cv + x2 * sv;
                    float o2 = -x1 * sv + x2 * cv;
                    o1a[nt][i] = o1;
                    o2a[nt][i] = o2;
                    ss += o1 * o1 + o2 * o2;
                }
            }
            ss += __shfl_xor_sync(0xffffffffu, ss, 1);
            ss += __shfl_xor_sync(0xffffffffu, ss, 2);
            float inv = rsqrtf(ss * (1.0f / HDim) + 1e-6f) * scl;

            __half* og = Og + (size_t)row * QKVN + hb;
#pragma unroll
            for (int nt = 0; nt < 4; nt++) {
                int d = nt * 8 + 2 * gc;
                *(__half2*)&og[d] =
                    __floats2half2_rn(o1a[nt][0] * inv, o1a[nt][1] * inv);
                *(__half2*)&og[d + 32] =
                    __floats2half2_rn(o2a[nt][0] * inv, o2a[nt][1] * inv);
            }
        }
    }
}

// ============================================================
// Wo GEMM: fp16 in, fp32 out.
// ============================================================
__global__ __launch_bounds__(128, 3) void gemm_wo(
    const __half* __restrict__ A, const __half* __restrict__ BT,
    float* __restrict__ C)
{
    GEMM_PROLOG
    GEMM_MAINLOOP(A, BT)

#pragma unroll
    for (int mt = 0; mt < 4; mt++)
#pragma unroll
        for (int nt = 0; nt < 8; nt++) {
            int row = bm + m0 + mt * 16 + gr;
            int col = bn + n0 + nt * 8 + 2 * gc;
            *(float2*)&C[(size_t)row * Cc + col] =
                make_float2(acc[mt][nt][0], acc[mt][nt][1]);
            *(float2*)&C[(size_t)(row + 8) * Cc + col] =
                make_float2(acc[mt][nt][2], acc[mt][nt][3]);
        }
}

// ============================================================
// fp16 flash attention: 128 threads, 4 warps x 32 q-rows,
// register-resident P, double-buffered KV, 1 barrier per tile.
// ============================================================
#define AST 72
#define QS_OFF 0
#define KS_OFF (128 * AST)
#define VS_OFF (KS_OFF + 2 * 64 * AST)
#define FLASH_SMEM ((128 * AST + 4 * 64 * AST) * 2)   // 55296 bytes

__global__ __launch_bounds__(128) void flash_attn_mma(
    const __half* __restrict__ QKV, __half* __restrict__ Og)
{
    extern __shared__ __half sm[];

    int qb = (gridDim.x - 1) - blockIdx.x;   // LPT: biggest first
    int h = blockIdx.y, b = blockIdx.z;
    int q0 = qb * 128;
    int kvh = h >> 2;
    int tid = threadIdx.x, wid = tid >> 5, lane = tid & 31;
    int gr = lane >> 2, gc = lane & 3;
    int m0 = wid * 32;
    const int aro = ((lane & 8) ? 8 : 0) + (lane & 7);
    const int aco = (lane & 16) ? 8 : 0;
    const int bro = ((lane & 16) ? 8 : 0) + (lane & 7);
    const int bco = (lane & 8) ? 8 : 0;

    const uint32_t sm_u = (uint32_t)__cvta_generic_to_shared(sm);
    const uint32_t Qs_u = sm_u + QS_OFF * 2;

    const __half* Qbase = QKV + (size_t)(b * Tt + q0) * QKVN + h * HDim;
    const __half* KVbase = QKV + (size_t)(b * Tt) * QKVN + 1024 + kvh * HDim;

#pragma unroll
    for (int i = 0; i < 8; i++) {
        int fi = i * 128 + tid;
        int row = fi >> 3, c8 = (fi & 7) * 8;
        cpa16(&sm[QS_OFF + row * AST + c8], Qbase + (size_t)row * QKVN + c8);
    }
    CP_COMMIT();

    auto issueKV = [&](int sbuf, int kt) {
        const __half* Kb = KVbase + (size_t)(kt * 64) * QKVN;
#pragma unroll
        for (int i = 0; i < 4; i++) {
            int fi = i * 128 + tid;
            int row = fi >> 3, c8 = (fi & 7) * 8;
            const __half* g = Kb + (size_t)row * QKVN + c8;
            cpa16(&sm[KS_OFF + sbuf * 64 * AST + row * AST + c8], g);
            cpa16(&sm[VS_OFF + sbuf * 64 * AST + row * AST + c8], g + 256);
        }
        CP_COMMIT();
    };

    issueKV(0, 0);
    CP_WAIT(1);
    __syncthreads();

    uint32_t qf[2][4][4];
#pragma unroll
    for (int mt = 0; mt < 2; mt++)
#pragma unroll
        for (int ks = 0; ks < 4; ks++)
            ldmx4(qf[mt][ks], Qs_u + 2 * ((m0 + mt * 16 + aro) * AST + ks * 16 + aco));

    float o[2][8][4];
#pragma unroll
    for (int mt = 0; mt < 2; mt++)
#pragma unroll
        for (int nt = 0; nt < 8; nt++)
#pragma unroll
            for (int i = 0; i < 4; i++) o[mt][nt][i] = 0.f;
    float mx[2][2], lsum[2][2];
#pragma unroll
    for (int mt = 0; mt < 2; mt++) {
        mx[mt][0] = -1e30f; mx[mt][1] = -1e30f;
        lsum[mt][0] = 0.f;  lsum[mt][1] = 0.f;
    }

    const int nkt = 2 * qb + 2;

    for (int kt = 0; kt < nkt; kt++) {
        int kv0 = kt * 64;
        int buf = kt & 1;
        CP_WAIT(0);
        __syncthreads();
        if (kt + 1 < nkt) issueKV(buf ^ 1, kt + 1);

        uint32_t Ks_u = sm_u + (KS_OFF + buf * 64 * AST) * 2;
        uint32_t Vs_u = sm_u + (VS_OFF + buf * 64 * AST) * 2;

        float s[2][8][4];
#pragma unroll
        for (int mt = 0; mt < 2; mt++)
#pragma unroll
            for (int nt = 0; nt < 8; nt++)
#pragma unroll
                for (int i = 0; i < 4; i++) s[mt][nt][i] = 0.f;

#pragma unroll
        for (int ks = 0; ks < 4; ks++) {
            uint32_t kf[4][4];
#pragma unroll
            for (int p = 0; p < 4; p++)
                ldmx4(kf[p], Ks_u + 2 * ((p * 16 + bro) * AST + ks * 16 + bco));
#pragma unroll
            for (int mt = 0; mt < 2; mt++)
#pragma unroll
                for (int nt = 0; nt < 8; nt++) {
                    int p = nt >> 1, hh = nt & 1;
                    mma16816(s[mt][nt],
                             qf[mt][ks][0], qf[mt][ks][1], qf[mt][ks][2], qf[mt][ks][3],
                             kf[p][2 * hh], kf[p][2 * hh + 1]);
                }
        }

        if (kv0 + 63 > q0) {
#pragma unroll
            for (int mt = 0; mt < 2; mt++) {
                int rl = q0 + m0 + mt * 16 + gr;
                int rh = rl + 8;
#pragma unroll
                for (int nt = 0; nt < 8; nt++) {
                    int c0 = kv0 + nt * 8 + 2 * gc;
                    if (c0 > rl)     s[mt][nt][0] = -1e30f;
                    if (c0 + 1 > rl) s[mt][nt][1] = -1e30f;
                    if (c0 > rh)     s[mt][nt][2] = -1e30f;
                    if (c0 + 1 > rh) s[mt][nt][3] = -1e30f;
                }
            }
        }

        uint32_t pf[2][4][4];
#pragma unroll
        for (int mt = 0; mt < 2; mt++) {
            float tlo = -1e30f, thi = -1e30f;
#pragma unroll
            for (int nt = 0; nt < 8; nt++) {
                tlo = fmaxf(tlo, fmaxf(s[mt][nt][0], s[mt][nt][1]));
                thi = fmaxf(thi, fmaxf(s[mt][nt][2], s[mt][nt][3]));
            }
            tlo = fmaxf(tlo, __shfl_xor_sync(0xffffffffu, tlo, 1));
            tlo = fmaxf(tlo, __shfl_xor_sync(0xffffffffu, tlo, 2));
            thi = fmaxf(thi, __shfl_xor_sync(0xffffffffu, thi, 1));
            thi = fmaxf(thi, __shfl_xor_sync(0xffffffffu, thi, 2));

            float mn_lo = fmaxf(mx[mt][0], tlo);
            float mn_hi = fmaxf(mx[mt][1], thi);
            float cor_lo = ex2f(mx[mt][0] - mn_lo);
            float cor_hi = ex2f(mx[mt][1] - mn_hi);
            mx[mt][0] = mn_lo; mx[mt][1] = mn_hi;
            lsum[mt][0] *= cor_lo; lsum[mt][1] *= cor_hi;
#pragma unroll
            for (int nt = 0; nt < 8; nt++) {
                o[mt][nt][0] *= cor_lo; o[mt][nt][1] *= cor_lo;
                o[mt][nt][2] *= cor_hi; o[mt][nt][3] *= cor_hi;
            }

#pragma unroll
            for (int ks = 0; ks < 4; ks++) {
                float a0 = ex2f(s[mt][2 * ks][0] - mn_lo);
                float a1 = ex2f(s[mt][2 * ks][1] - mn_lo);
                float a2 = ex2f(s[mt][2 * ks][2] - mn_hi);
                float a3 = ex2f(s[mt][2 * ks][3] - mn_hi);
                float b0 = ex2f(s[mt][2 * ks + 1][0] - mn_lo);
                float b1 = ex2f(s[mt][2 * ks + 1][1] - mn_lo);
                float b2 = ex2f(s[mt][2 * ks + 1][2] - mn_hi);
                float b3 = ex2f(s[mt][2 * ks + 1][3] - mn_hi);
                lsum[mt][0] += a0 + a1 + b0 + b1;
                lsum[mt][1] += a2 + a3 + b2 + b3;
                pf[mt][ks][0] = packh2(a0, a1);
                pf[mt][ks][1] = packh2(a2, a3);
                pf[mt][ks][2] = packh2(b0, b1);
                pf[mt][ks][3] = packh2(b2, b3);
            }
        }

#pragma unroll
        for (int ks = 0; ks < 4; ks++) {
            uint32_t vf[4][4];
#pragma unroll
            for (int p = 0; p < 4; p++)
                ldmx4t(vf[p], Vs_u + 2 * ((ks * 16 + aro) * AST + p * 16 + aco));
#pragma unroll
            for (int mt = 0; mt < 2; mt++)
#pragma unroll
                for (int nt = 0; nt < 8; nt++) {
                    int p = nt >> 1, hh = nt & 1;
                    mma16816(o[mt][nt],
                             pf[mt][ks][0], pf[mt][ks][1], pf[mt][ks][2], pf[mt][ks][3],
                             vf[p][2 * hh], vf[p][2 * hh + 1]);
                }
        }
    }

    __half* Obase = Og + ((size_t)(b * Tt) * Hh + h) * HDim;
#pragma unroll
    for (int mt = 0; mt < 2; mt++) {
        float llo = lsum[mt][0], lhi = lsum[mt][1];
        llo += __shfl_xor_sync(0xffffffffu, llo, 1);
        llo += __shfl_xor_sync(0xffffffffu, llo, 2);
        lhi += __shfl_xor_sync(0xffffffffu, lhi, 1);
        lhi += __shfl_xor_sync(0xffffffffu, lhi, 2);
        float inv_lo = 1.f / llo;
        float inv_hi = 1.f / lhi;

        int row_lo = q0 + m0 + mt * 16 + gr;
        int row_hi = row_lo + 8;
#pragma unroll
        for (int nt = 0; nt < 8; nt++) {
            int col = nt * 8 + 2 * gc;
            *(__half2*)&Obase[(size_t)row_lo * (Hh * HDim) + col] =
                __floats2half2_rn(o[mt][nt][0] * inv_lo, o[mt][nt][1] * inv_lo);
            *(__half2*)&Obase[(size_t)row_hi * (Hh * HDim) + col] =
                __floats2half2_rn(o[mt][nt][2] * inv_hi, o[mt][nt][3] * inv_hi);
        }
    }
}

// ============================================================
// launch
// ============================================================
extern "C" void kernel_launch(void* const* d_in, const int* in_sizes, int n_in,
                              void* d_out, int out_size)
{
    const float* x  = (const float*)d_in[0];
    const float* cs = (const float*)d_in[1];
    const float* sn = (const float*)d_in[2];
    const float* Wq = (const float*)d_in[3];
    const float* Wk = (const float*)d_in[4];
    const float* Wv = (const float*)d_in[5];
    const float* Wo = (const float*)d_in[6];
    float* out = (float*)d_out;

    __half *Xh, *QKVh, *Yh, *WqkvTh, *WoTh;
    cudaGetSymbolAddress((void**)&Xh, g_Xh);
    cudaGetSymbolAddress((void**)&QKVh, g_QKVh);
    cudaGetSymbolAddress((void**)&Yh, g_Yh);
    cudaGetSymbolAddress((void**)&WqkvTh, g_WqkvTh);
    cudaGetSymbolAddress((void**)&WoTh, g_WoTh);

    cudaFuncSetAttribute(gemm_qkv,
                         cudaFuncAttributeMaxDynamicSharedMemorySize, GEMM_SMEM);
    cudaFuncSetAttribute(gemm_wo,
                         cudaFuncAttributeMaxDynamicSharedMemorySize, GEMM_SMEM);
    cudaFuncSetAttribute(flash_attn_mma,
                         cudaFuncAttributeMaxDynamicSharedMemorySize, FLASH_SMEM);

    const int M = Bsz * Tt;  // 4096

    // fused prep: x->fp16 + both weight transposes in one launch
    prep<<<PREP_GRID, 256>>>(x, Wq, Wk, Wv, Wo, Xh, WqkvTh, WoTh);

    // fused QKV projection + rope + rms -> fp16 (Q pre-scaled)
    gemm_qkv<<<dim3(QKVN / 128, M / 128), 128, GEMM_SMEM>>>(Xh, WqkvTh, QKVh, cs, sn);

    // causal GQA flash attention (register-resident P)
    flash_attn_mma<<<dim3(Tt / 128, Hh, Bsz), 128, FLASH_SMEM>>>(QKVh, Yh);

    // output projection
    gemm_wo<<<dim3(Cc / 128, M / 128), 128, GEMM_SMEM>>>(Yh, WoTh, out);
}